// round 5
// baseline (speedup 1.0000x reference)
#include <cuda_runtime.h>
#include <math.h>

#define N    8192
#define LOGN 13
#define NT   256
#define SRf  30.0f
#define PI_F 3.14159265358979f

// ---------------- block reductions (deterministic, no float atomics) ----------
__device__ __forceinline__ float bredSumF(float v) {
    __shared__ float scr[8];
    int lane = threadIdx.x & 31, w = threadIdx.x >> 5;
    #pragma unroll
    for (int o = 16; o; o >>= 1) v += __shfl_down_sync(0xffffffffu, v, o);
    __syncthreads();
    if (lane == 0) scr[w] = v;
    __syncthreads();
    if (threadIdx.x == 0) {
        float r = scr[0];
        #pragma unroll
        for (int i = 1; i < NT / 32; i++) r += scr[i];
        scr[0] = r;
    }
    __syncthreads();
    v = scr[0];
    __syncthreads();
    return v;
}

__device__ __forceinline__ float bredMaxF(float v) {
    __shared__ float scr[8];
    int lane = threadIdx.x & 31, w = threadIdx.x >> 5;
    #pragma unroll
    for (int o = 16; o; o >>= 1) v = fmaxf(v, __shfl_down_sync(0xffffffffu, v, o));
    __syncthreads();
    if (lane == 0) scr[w] = v;
    __syncthreads();
    if (threadIdx.x == 0) {
        float r = scr[0];
        #pragma unroll
        for (int i = 1; i < NT / 32; i++) r = fmaxf(r, scr[i]);
        scr[0] = r;
    }
    __syncthreads();
    v = scr[0];
    __syncthreads();
    return v;
}

__device__ __forceinline__ float bredMinF(float v) {
    __shared__ float scr[8];
    int lane = threadIdx.x & 31, w = threadIdx.x >> 5;
    #pragma unroll
    for (int o = 16; o; o >>= 1) v = fminf(v, __shfl_down_sync(0xffffffffu, v, o));
    __syncthreads();
    if (lane == 0) scr[w] = v;
    __syncthreads();
    if (threadIdx.x == 0) {
        float r = scr[0];
        #pragma unroll
        for (int i = 1; i < NT / 32; i++) r = fminf(r, scr[i]);
        scr[0] = r;
    }
    __syncthreads();
    v = scr[0];
    __syncthreads();
    return v;
}

__device__ __forceinline__ int bredSumI(int v) {
    __shared__ int scr[8];
    int lane = threadIdx.x & 31, w = threadIdx.x >> 5;
    #pragma unroll
    for (int o = 16; o; o >>= 1) v += __shfl_down_sync(0xffffffffu, v, o);
    __syncthreads();
    if (lane == 0) scr[w] = v;
    __syncthreads();
    if (threadIdx.x == 0) {
        int r = scr[0];
        #pragma unroll
        for (int i = 1; i < NT / 32; i++) r += scr[i];
        scr[0] = r;
    }
    __syncthreads();
    v = scr[0];
    __syncthreads();
    return v;
}

__device__ __forceinline__ int bredMinI(int v) {
    __shared__ int scr[8];
    int lane = threadIdx.x & 31, w = threadIdx.x >> 5;
    #pragma unroll
    for (int o = 16; o; o >>= 1) v = min(v, __shfl_down_sync(0xffffffffu, v, o));
    __syncthreads();
    if (lane == 0) scr[w] = v;
    __syncthreads();
    if (threadIdx.x == 0) {
        int r = scr[0];
        #pragma unroll
        for (int i = 1; i < NT / 32; i++) r = min(r, scr[i]);
        scr[0] = r;
    }
    __syncthreads();
    v = scr[0];
    __syncthreads();
    return v;
}

__device__ __forceinline__ int bredMaxI(int v) {
    __shared__ int scr[8];
    int lane = threadIdx.x & 31, w = threadIdx.x >> 5;
    #pragma unroll
    for (int o = 16; o; o >>= 1) v = max(v, __shfl_down_sync(0xffffffffu, v, o));
    __syncthreads();
    if (lane == 0) scr[w] = v;
    __syncthreads();
    if (threadIdx.x == 0) {
        int r = scr[0];
        #pragma unroll
        for (int i = 1; i < NT / 32; i++) r = max(r, scr[i]);
        scr[0] = r;
    }
    __syncthreads();
    v = scr[0];
    __syncthreads();
    return v;
}

// ---------------- main kernel: one CTA per row -------------------------------
__global__ __launch_bounds__(NT)
void feat_kernel(const float* __restrict__ xin, float* __restrict__ out, int nrows) {
    extern __shared__ float smem[];
    float* re = smem;        // [N]
    float* im = smem + N;    // [N]

    int row = blockIdx.x;
    if (row >= nrows) return;
    const float* x = xin + (size_t)row * N;
    int tid = threadIdx.x;

    // ---- pass 1: load + max/min/sum/sumsq -------------------------------
    float mx = -3.4e38f, mn = 3.4e38f, s = 0.f, s2 = 0.f;
    for (int i = tid; i < N; i += NT) {
        float v = x[i];
        re[i] = v;
        im[i] = 0.f;
        mx = fmaxf(mx, v);
        mn = fminf(mn, v);
        s  += v;
        s2 += v * v;
    }
    __syncthreads();
    mx = bredMaxF(mx);
    mn = bredMinF(mn);
    s  = bredSumF(s);
    s2 = bredSumF(s2);

    // ---- pass 2: peak/valley detection ----------------------------------
    int npk = 0, nvl = 0, p0 = N, v0 = N, vlast = -1;
    for (int i = tid; i < N; i += NT) {
        if (i >= 1 && i <= N - 2) {
            float c = re[i], l = re[i - 1], r = re[i + 1];
            if (c > l && c > r) { npk++; p0 = min(p0, i); }
            if (c < l && c < r) { nvl++; v0 = min(v0, i); vlast = max(vlast, i); }
        }
    }
    npk   = bredSumI(npk);
    nvl   = bredSumI(nvl);
    p0    = bredMinI(p0);
    v0    = bredMinI(v0);
    vlast = bredMaxI(vlast);

    bool valid = (npk >= 1) && (nvl >= 2);

    float PA = 0.f, A2 = 0.f, A1 = 0.f, PH = 0.f, PWHH = 0.f;

    if (valid) {
        // ---- pass 3: second valley (first valley with index > v0) -------
        int v1 = N;
        for (int i = tid; i < N; i += NT) {
            if (i > v0 && i >= 1 && i <= N - 2) {
                float c = re[i];
                if (c < re[i - 1] && c < re[i + 1]) v1 = min(v1, i);
            }
        }
        v1 = bredMinI(v1);

        float sp0 = re[p0];
        float sv0 = re[v0];
        PH = sp0 - sv0;
        float hh = (sp0 + sv0) * 0.5f;

        // ---- pass 4: trapezoid sums + half-height indices ----------------
        float pa = 0.f, a2 = 0.f, a1 = 0.f;
        int li = N, ri = -1;
        for (int i = tid; i < N; i += NT) {
            float c = re[i];
            if (i < N - 1) {
                float seg = (c + re[i + 1]) * (0.5f / SRf);
                if (i >= v0 && i <= vlast - 2) pa += seg;
                if (i >= p0 && i <= v1 - 2)    a2 += seg;
                if (i >= v0 && i <= p0 - 2)    a1 += seg;
            }
            if (c >= hh) {
                if (i >= v0 && i < p0)  li = min(li, i);
                if (i > v0 && i <= p0)  ri = max(ri, i);
            }
        }
        PA = bredSumF(pa);
        A2 = bredSumF(a2);
        A1 = bredSumF(a1);
        li = bredMinI(li);
        ri = bredMaxI(ri);
        if (li == N)  li = v0;   // no element satisfied mask
        if (ri == -1) ri = p0;
        PWHH = (float)(ri - li) / SRf;
    }
    __syncthreads();

    // ---- FFT: in-place radix-2 DIF (natural in, bit-reversed out) -------
    // output order irrelevant: we only need sum of magnitudes.
    for (int stage = 0; stage < LOGN; stage++) {
        int size_log = LOGN - stage;
        int half_log = size_log - 1;
        int half = 1 << half_log;
        for (int b = tid; b < N / 2; b += NT) {
            int t = b & (half - 1);
            int base = (b >> half_log) << size_log;
            int i0 = base + t;
            int i1 = i0 + half;
            float ur = re[i0], ui = im[i0];
            float vr = re[i1], vi = im[i1];
            re[i0] = ur + vr;
            im[i0] = ui + vi;
            float dr = ur - vr, di = ui - vi;
            float ang = -PI_F * (float)t / (float)half;  // -2*pi*t/size
            float sn, cs;
            sincosf(ang, &sn, &cs);
            re[i1] = dr * cs - di * sn;
            im[i1] = dr * sn + di * cs;
        }
        __syncthreads();
    }

    // ---- magnitude mean --------------------------------------------------
    float fs = 0.f;
    for (int i = tid; i < N; i += NT) {
        float a = re[i], b = im[i];
        fs += sqrtf(a * a + b * b);
    }
    fs = bredSumF(fs);
    float fftm = fs * (1.0f / (float)N);

    // ---- write output ----------------------------------------------------
    if (tid == 0) {
        float mean = s * (1.0f / (float)N);
        float var  = (s2 - s * mean) * (1.0f / (float)(N - 1));
        float sd   = sqrtf(var);
        float* o = out + (size_t)row * 10;
        o[0] = mx;
        o[1] = mx - mn;
        o[2] = var;
        o[3] = sd;
        o[4] = fftm;
        o[5] = valid ? PA : 0.f;
        o[6] = valid ? A2 : 0.f;
        o[7] = valid ? PH : 0.f;
        o[8] = valid ? A1 : 0.f;
        o[9] = valid ? PWHH : 0.f;
    }
}

extern "C" void kernel_launch(void* const* d_in, const int* in_sizes, int n_in,
                              void* d_out, int out_size) {
    const float* x = (const float*)d_in[0];
    float* out = (float*)d_out;
    int nrows = in_sizes[0] / N;  // 2048
    size_t smem_bytes = 2 * (size_t)N * sizeof(float);  // 64 KB
    cudaFuncSetAttribute(feat_kernel, cudaFuncAttributeMaxDynamicSharedMemorySize,
                         (int)smem_bytes);
    feat_kernel<<<nrows, NT, smem_bytes>>>(x, out, nrows);
}

// round 7
// speedup vs baseline: 2.6773x; 2.6773x over previous
#include <cuda_runtime.h>
#include <math.h>

#define N     8192          // real signal length
#define M     4096          // packed complex length
#define NT    256
#define SRf   30.0f
#define PI_F  3.14159265358979f
#define C8    0.70710678118654752f   // sqrt(2)/2

// padded complex offset: one extra float2 per 8 -> conflict-free pass strides
#define POFF(n)  ((n) + ((n) >> 3))
// scalar view of x[i] inside the padded complex buffer (z[n].x=x[2n], .y=x[2n+1])
#define XIDX(i)  (((((i) >> 1) + ((i) >> 4)) << 1) | ((i) & 1))

#define SMEM_F2  (M + M / 8)         // 4608 float2 = 36864 B

// ---------------- block reductions (deterministic) ---------------------------
__device__ __forceinline__ float bredSumF(float v) {
    __shared__ float scr[8];
    int lane = threadIdx.x & 31, w = threadIdx.x >> 5;
    #pragma unroll
    for (int o = 16; o; o >>= 1) v += __shfl_down_sync(0xffffffffu, v, o);
    __syncthreads();
    if (lane == 0) scr[w] = v;
    __syncthreads();
    if (threadIdx.x == 0) {
        float r = scr[0];
        #pragma unroll
        for (int i = 1; i < NT / 32; i++) r += scr[i];
        scr[0] = r;
    }
    __syncthreads();
    v = scr[0];
    __syncthreads();
    return v;
}
__device__ __forceinline__ float bredMaxF(float v) {
    __shared__ float scr[8];
    int lane = threadIdx.x & 31, w = threadIdx.x >> 5;
    #pragma unroll
    for (int o = 16; o; o >>= 1) v = fmaxf(v, __shfl_down_sync(0xffffffffu, v, o));
    __syncthreads();
    if (lane == 0) scr[w] = v;
    __syncthreads();
    if (threadIdx.x == 0) {
        float r = scr[0];
        #pragma unroll
        for (int i = 1; i < NT / 32; i++) r = fmaxf(r, scr[i]);
        scr[0] = r;
    }
    __syncthreads();
    v = scr[0];
    __syncthreads();
    return v;
}
__device__ __forceinline__ float bredMinF(float v) {
    __shared__ float scr[8];
    int lane = threadIdx.x & 31, w = threadIdx.x >> 5;
    #pragma unroll
    for (int o = 16; o; o >>= 1) v = fminf(v, __shfl_down_sync(0xffffffffu, v, o));
    __syncthreads();
    if (lane == 0) scr[w] = v;
    __syncthreads();
    if (threadIdx.x == 0) {
        float r = scr[0];
        #pragma unroll
        for (int i = 1; i < NT / 32; i++) r = fminf(r, scr[i]);
        scr[0] = r;
    }
    __syncthreads();
    v = scr[0];
    __syncthreads();
    return v;
}
__device__ __forceinline__ int bredSumI(int v) {
    __shared__ int scr[8];
    int lane = threadIdx.x & 31, w = threadIdx.x >> 5;
    #pragma unroll
    for (int o = 16; o; o >>= 1) v += __shfl_down_sync(0xffffffffu, v, o);
    __syncthreads();
    if (lane == 0) scr[w] = v;
    __syncthreads();
    if (threadIdx.x == 0) {
        int r = scr[0];
        #pragma unroll
        for (int i = 1; i < NT / 32; i++) r += scr[i];
        scr[0] = r;
    }
    __syncthreads();
    v = scr[0];
    __syncthreads();
    return v;
}
__device__ __forceinline__ int bredMinI(int v) {
    __shared__ int scr[8];
    int lane = threadIdx.x & 31, w = threadIdx.x >> 5;
    #pragma unroll
    for (int o = 16; o; o >>= 1) v = min(v, __shfl_down_sync(0xffffffffu, v, o));
    __syncthreads();
    if (lane == 0) scr[w] = v;
    __syncthreads();
    if (threadIdx.x == 0) {
        int r = scr[0];
        #pragma unroll
        for (int i = 1; i < NT / 32; i++) r = min(r, scr[i]);
        scr[0] = r;
    }
    __syncthreads();
    v = scr[0];
    __syncthreads();
    return v;
}
__device__ __forceinline__ int bredMaxI(int v) {
    __shared__ int scr[8];
    int lane = threadIdx.x & 31, w = threadIdx.x >> 5;
    #pragma unroll
    for (int o = 16; o; o >>= 1) v = max(v, __shfl_down_sync(0xffffffffu, v, o));
    __syncthreads();
    if (lane == 0) scr[w] = v;
    __syncthreads();
    if (threadIdx.x == 0) {
        int r = scr[0];
        #pragma unroll
        for (int i = 1; i < NT / 32; i++) r = max(r, scr[i]);
        scr[0] = r;
    }
    __syncthreads();
    v = scr[0];
    __syncthreads();
    return v;
}

// ---------------- complex helpers -------------------------------------------
__device__ __forceinline__ float2 cadd(float2 a, float2 b) { return make_float2(a.x + b.x, a.y + b.y); }
__device__ __forceinline__ float2 csub(float2 a, float2 b) { return make_float2(a.x - b.x, a.y - b.y); }
__device__ __forceinline__ float2 cmul(float2 a, float2 b) {
    return make_float2(a.x * b.x - a.y * b.y, a.x * b.y + a.y * b.x);
}

// one radix-8 DIF pass over the 4096-pt complex array (padded layout).
// L = current transform size, S = L/8, LOG2S = log2(S).
template<int L, int LOG2S, bool TW>
__device__ __forceinline__ void radix8_pass(float2* __restrict__ z, int tid) {
    const int S = L / 8;
    #pragma unroll
    for (int rep = 0; rep < M / 8 / NT; rep++) {     // 2 butterflies / thread
        int b   = tid + rep * NT;
        int t   = b & (S - 1);
        int blk = b >> LOG2S;
        int base = blk * L + t;

        float2 x0 = z[POFF(base + 0 * S)];
        float2 x1 = z[POFF(base + 1 * S)];
        float2 x2 = z[POFF(base + 2 * S)];
        float2 x3 = z[POFF(base + 3 * S)];
        float2 x4 = z[POFF(base + 4 * S)];
        float2 x5 = z[POFF(base + 5 * S)];
        float2 x6 = z[POFF(base + 6 * S)];
        float2 x7 = z[POFF(base + 7 * S)];

        float2 t0 = cadd(x0, x4), t4 = csub(x0, x4);
        float2 t1 = cadd(x1, x5), t5 = csub(x1, x5);
        float2 t2 = cadd(x2, x6), t6 = csub(x2, x6);
        float2 t3 = cadd(x3, x7), t7 = csub(x3, x7);

        // even outputs (y0,y2,y4,y6): 4-pt DFT of t0..t3
        float2 u0 = cadd(t0, t2), u2 = csub(t0, t2);
        float2 u1 = cadd(t1, t3), u3 = csub(t1, t3);
        float2 y0 = cadd(u0, u1);
        float2 y4 = csub(u0, u1);
        float2 y2 = make_float2(u2.x + u3.y, u2.y - u3.x);   // u2 - i*u3
        float2 y6 = make_float2(u2.x - u3.y, u2.y + u3.x);   // u2 + i*u3

        // odd outputs: w_m = t_{4+m} * w8^m, then 4-pt DFT
        float2 w0 = t4;
        float2 w1 = make_float2(C8 * (t5.x + t5.y), C8 * (t5.y - t5.x));   // *(c - ci)
        float2 w2 = make_float2(t6.y, -t6.x);                              // *(-i)
        float2 w3 = make_float2(C8 * (t7.y - t7.x), -C8 * (t7.x + t7.y));  // *(-c - ci)
        float2 p0 = cadd(w0, w2), p2 = csub(w0, w2);
        float2 p1 = cadd(w1, w3), p3 = csub(w1, w3);
        float2 y1 = cadd(p0, p1);
        float2 y5 = csub(p0, p1);
        float2 y3 = make_float2(p2.x + p3.y, p2.y - p3.x);
        float2 y7 = make_float2(p2.x - p3.y, p2.y + p3.x);

        if (TW) {
            float sn, cs;
            __sincosf(-2.0f * PI_F * (float)t / (float)L, &sn, &cs);
            float2 tw1 = make_float2(cs, sn);
            float2 tw2 = cmul(tw1, tw1);
            float2 tw3 = cmul(tw2, tw1);
            float2 tw4 = cmul(tw2, tw2);
            float2 tw5 = cmul(tw3, tw2);
            float2 tw6 = cmul(tw3, tw3);
            float2 tw7 = cmul(tw4, tw3);
            y1 = cmul(y1, tw1);
            y2 = cmul(y2, tw2);
            y3 = cmul(y3, tw3);
            y4 = cmul(y4, tw4);
            y5 = cmul(y5, tw5);
            y6 = cmul(y6, tw6);
            y7 = cmul(y7, tw7);
        }

        z[POFF(base + 0 * S)] = y0;
        z[POFF(base + 1 * S)] = y1;
        z[POFF(base + 2 * S)] = y2;
        z[POFF(base + 3 * S)] = y3;
        z[POFF(base + 4 * S)] = y4;
        z[POFF(base + 5 * S)] = y5;
        z[POFF(base + 6 * S)] = y6;
        z[POFF(base + 7 * S)] = y7;
    }
}

// octal digit reverse of 12-bit index (4 radix-8 DIF passes -> digit-reversed)
__device__ __forceinline__ int drev(int k) {
    return ((k & 7) << 9) | (((k >> 3) & 7) << 6) | (((k >> 6) & 7) << 3) | ((k >> 9) & 7);
}

// ---------------- main kernel: one CTA per row -------------------------------
__global__ __launch_bounds__(NT)
void feat_kernel(const float* __restrict__ xin, float* __restrict__ out, int nrows) {
    extern __shared__ float smf[];           // SMEM_F2 float2 = 36864 B
    float2* z = (float2*)smf;

    int row = blockIdx.x;
    if (row >= nrows) return;
    const float* x = xin + (size_t)row * N;
    int tid = threadIdx.x;

    // ---- pass 1: load + max/min/sum/sumsq (padded scalar layout) --------
    float mx = -3.4e38f, mn = 3.4e38f, s = 0.f, s2 = 0.f;
    for (int i = tid; i < N; i += NT) {
        float v = x[i];
        smf[XIDX(i)] = v;
        mx = fmaxf(mx, v);
        mn = fminf(mn, v);
        s  += v;
        s2 += v * v;
    }
    __syncthreads();
    mx = bredMaxF(mx);
    mn = bredMinF(mn);
    s  = bredSumF(s);
    s2 = bredSumF(s2);

    // ---- pass 2: peak/valley detection ----------------------------------
    int npk = 0, nvl = 0, p0 = N, v0 = N, vlast = -1;
    for (int i = tid; i < N; i += NT) {
        if (i >= 1 && i <= N - 2) {
            float c = smf[XIDX(i)], l = smf[XIDX(i - 1)], r = smf[XIDX(i + 1)];
            if (c > l && c > r) { npk++; p0 = min(p0, i); }
            if (c < l && c < r) { nvl++; v0 = min(v0, i); vlast = max(vlast, i); }
        }
    }
    npk   = bredSumI(npk);
    nvl   = bredSumI(nvl);
    p0    = bredMinI(p0);
    v0    = bredMinI(v0);
    vlast = bredMaxI(vlast);

    bool valid = (npk >= 1) && (nvl >= 2);
    float PA = 0.f, A2 = 0.f, A1 = 0.f, PH = 0.f, PWHH = 0.f;

    if (valid) {
        // ---- pass 3: second valley --------------------------------------
        int v1 = N;
        for (int i = tid; i < N; i += NT) {
            if (i > v0 && i >= 1 && i <= N - 2) {
                float c = smf[XIDX(i)];
                if (c < smf[XIDX(i - 1)] && c < smf[XIDX(i + 1)]) v1 = min(v1, i);
            }
        }
        v1 = bredMinI(v1);

        float sp0 = smf[XIDX(p0)];
        float sv0 = smf[XIDX(v0)];
        PH = sp0 - sv0;
        float hh = (sp0 + sv0) * 0.5f;

        // ---- pass 4: trapezoid sums + half-height indices ----------------
        float pa = 0.f, a2 = 0.f, a1 = 0.f;
        int li = N, ri = -1;
        for (int i = tid; i < N; i += NT) {
            float c = smf[XIDX(i)];
            if (i < N - 1) {
                float seg = (c + smf[XIDX(i + 1)]) * (0.5f / SRf);
                if (i >= v0 && i <= vlast - 2) pa += seg;
                if (i >= p0 && i <= v1 - 2)    a2 += seg;
                if (i >= v0 && i <= p0 - 2)    a1 += seg;
            }
            if (c >= hh) {
                if (i >= v0 && i < p0)  li = min(li, i);
                if (i > v0 && i <= p0)  ri = max(ri, i);
            }
        }
        PA = bredSumF(pa);
        A2 = bredSumF(a2);
        A1 = bredSumF(a1);
        li = bredMinI(li);
        ri = bredMaxI(ri);
        if (li == N)  li = v0;
        if (ri == -1) ri = p0;
        PWHH = (float)(ri - li) / SRf;
    }
    __syncthreads();

    // ---- FFT: z[n] = x[2n] + i x[2n+1], 4096-pt, 4 radix-8 DIF passes ----
    radix8_pass<4096, 9, true >(z, tid);  __syncthreads();
    radix8_pass< 512, 6, true >(z, tid);  __syncthreads();
    radix8_pass<  64, 3, true >(z, tid);  __syncthreads();
    radix8_pass<   8, 0, false>(z, tid);  __syncthreads();

    // ---- unpack real FFT + magnitude sum ---------------------------------
    // X[k]   = Ze + W_N^k Zo,  X[k+M] = Ze - W_N^k Zo, k = 0..M-1
    // Ze = (Z[k] + conj(Z[M-k]))/2,  Zo = -i (Z[k] - conj(Z[M-k]))/2
    float fs = 0.f;
    #pragma unroll
    for (int rep = 0; rep < M / NT; rep++) {
        int k  = tid + rep * NT;
        int km = (M - k) & (M - 1);
        float2 Zk = z[POFF(drev(k))];
        float2 Zm = z[POFF(drev(km))];
        float2 Ze = make_float2(0.5f * (Zk.x + Zm.x), 0.5f * (Zk.y - Zm.y));
        float2 Bv = make_float2(0.5f * (Zk.x - Zm.x), 0.5f * (Zk.y + Zm.y));
        float2 Zo = make_float2(Bv.y, -Bv.x);
        float sn, cs;
        __sincosf(-PI_F * (float)k / (float)M, &sn, &cs);
        float2 WZo = cmul(make_float2(cs, sn), Zo);
        float ax = Ze.x + WZo.x, ay = Ze.y + WZo.y;
        float bx = Ze.x - WZo.x, by = Ze.y - WZo.y;
        fs += sqrtf(ax * ax + ay * ay) + sqrtf(bx * bx + by * by);
    }
    fs = bredSumF(fs);
    float fftm = fs * (1.0f / (float)N);

    // ---- write output ----------------------------------------------------
    if (tid == 0) {
        float mean = s * (1.0f / (float)N);
        float var  = (s2 - s * mean) * (1.0f / (float)(N - 1));
        float sd   = sqrtf(var);
        float* o = out + (size_t)row * 10;
        o[0] = mx;
        o[1] = mx - mn;
        o[2] = var;
        o[3] = sd;
        o[4] = fftm;
        o[5] = valid ? PA : 0.f;
        o[6] = valid ? A2 : 0.f;
        o[7] = valid ? PH : 0.f;
        o[8] = valid ? A1 : 0.f;
        o[9] = valid ? PWHH : 0.f;
    }
}

extern "C" void kernel_launch(void* const* d_in, const int* in_sizes, int n_in,
                              void* d_out, int out_size) {
    const float* x = (const float*)d_in[0];
    float* out = (float*)d_out;
    int nrows = in_sizes[0] / N;  // 2048
    size_t smem_bytes = (size_t)SMEM_F2 * sizeof(float2);  // 36864 B
    cudaFuncSetAttribute(feat_kernel, cudaFuncAttributeMaxDynamicSharedMemorySize,
                         (int)smem_bytes);
    feat_kernel<<<nrows, NT, smem_bytes>>>(x, out, nrows);
}

// round 8
// speedup vs baseline: 3.9665x; 1.4815x over previous
#include <cuda_runtime.h>
#include <math.h>

#define N     8192          // real signal length
#define M     4096          // packed complex length
#define NT    256
#define SRf   30.0f
#define PI_F  3.14159265358979f
#define C8    0.70710678118654752f   // sqrt(2)/2

// padded complex offset: one extra float2 per 8 -> conflict-free pass strides
#define POFF(n)  ((n) + ((n) >> 3))
// scalar view of x[i] inside the padded complex buffer (z[n].x=x[2n], .y=x[2n+1])
#define XIDX(i)  (((((i) >> 1) + ((i) >> 4)) << 1) | ((i) & 1))

#define SMEM_F2  (M + M / 8)         // 4608 float2 = 36864 B

__device__ __forceinline__ float fsqrt_ap(float x) {
    float r; asm("sqrt.approx.f32 %0, %1;" : "=f"(r) : "f"(x)); return r;
}

// ---------------- block reductions (deterministic) ---------------------------
__device__ __forceinline__ float bredSumF(float v) {
    __shared__ float scr[8];
    int lane = threadIdx.x & 31, w = threadIdx.x >> 5;
    #pragma unroll
    for (int o = 16; o; o >>= 1) v += __shfl_down_sync(0xffffffffu, v, o);
    __syncthreads();
    if (lane == 0) scr[w] = v;
    __syncthreads();
    if (threadIdx.x == 0) {
        float r = scr[0];
        #pragma unroll
        for (int i = 1; i < NT / 32; i++) r += scr[i];
        scr[0] = r;
    }
    __syncthreads();
    v = scr[0];
    __syncthreads();
    return v;
}
__device__ __forceinline__ float bredMaxF(float v) {
    __shared__ float scr[8];
    int lane = threadIdx.x & 31, w = threadIdx.x >> 5;
    #pragma unroll
    for (int o = 16; o; o >>= 1) v = fmaxf(v, __shfl_down_sync(0xffffffffu, v, o));
    __syncthreads();
    if (lane == 0) scr[w] = v;
    __syncthreads();
    if (threadIdx.x == 0) {
        float r = scr[0];
        #pragma unroll
        for (int i = 1; i < NT / 32; i++) r = fmaxf(r, scr[i]);
        scr[0] = r;
    }
    __syncthreads();
    v = scr[0];
    __syncthreads();
    return v;
}
__device__ __forceinline__ float bredMinF(float v) {
    __shared__ float scr[8];
    int lane = threadIdx.x & 31, w = threadIdx.x >> 5;
    #pragma unroll
    for (int o = 16; o; o >>= 1) v = fminf(v, __shfl_down_sync(0xffffffffu, v, o));
    __syncthreads();
    if (lane == 0) scr[w] = v;
    __syncthreads();
    if (threadIdx.x == 0) {
        float r = scr[0];
        #pragma unroll
        for (int i = 1; i < NT / 32; i++) r = fminf(r, scr[i]);
        scr[0] = r;
    }
    __syncthreads();
    v = scr[0];
    __syncthreads();
    return v;
}
__device__ __forceinline__ int bredSumI(int v) {
    __shared__ int scr[8];
    int lane = threadIdx.x & 31, w = threadIdx.x >> 5;
    #pragma unroll
    for (int o = 16; o; o >>= 1) v += __shfl_down_sync(0xffffffffu, v, o);
    __syncthreads();
    if (lane == 0) scr[w] = v;
    __syncthreads();
    if (threadIdx.x == 0) {
        int r = scr[0];
        #pragma unroll
        for (int i = 1; i < NT / 32; i++) r += scr[i];
        scr[0] = r;
    }
    __syncthreads();
    v = scr[0];
    __syncthreads();
    return v;
}
__device__ __forceinline__ int bredMinI(int v) {
    __shared__ int scr[8];
    int lane = threadIdx.x & 31, w = threadIdx.x >> 5;
    #pragma unroll
    for (int o = 16; o; o >>= 1) v = min(v, __shfl_down_sync(0xffffffffu, v, o));
    __syncthreads();
    if (lane == 0) scr[w] = v;
    __syncthreads();
    if (threadIdx.x == 0) {
        int r = scr[0];
        #pragma unroll
        for (int i = 1; i < NT / 32; i++) r = min(r, scr[i]);
        scr[0] = r;
    }
    __syncthreads();
    v = scr[0];
    __syncthreads();
    return v;
}
__device__ __forceinline__ int bredMaxI(int v) {
    __shared__ int scr[8];
    int lane = threadIdx.x & 31, w = threadIdx.x >> 5;
    #pragma unroll
    for (int o = 16; o; o >>= 1) v = max(v, __shfl_down_sync(0xffffffffu, v, o));
    __syncthreads();
    if (lane == 0) scr[w] = v;
    __syncthreads();
    if (threadIdx.x == 0) {
        int r = scr[0];
        #pragma unroll
        for (int i = 1; i < NT / 32; i++) r = max(r, scr[i]);
        scr[0] = r;
    }
    __syncthreads();
    v = scr[0];
    __syncthreads();
    return v;
}
// two smallest values across block (s1 <= s2 per thread on entry)
__device__ __forceinline__ void bredMin2I(int& s1, int& s2) {
    __shared__ int scr2[16];
    int lane = threadIdx.x & 31, w = threadIdx.x >> 5;
    #pragma unroll
    for (int o = 16; o; o >>= 1) {
        int o1 = __shfl_down_sync(0xffffffffu, s1, o);
        int o2 = __shfl_down_sync(0xffffffffu, s2, o);
        int n1 = min(s1, o1);
        int n2 = min(max(s1, o1), min(s2, o2));
        s1 = n1; s2 = n2;
    }
    __syncthreads();
    if (lane == 0) { scr2[w * 2] = s1; scr2[w * 2 + 1] = s2; }
    __syncthreads();
    if (threadIdx.x == 0) {
        int a1 = scr2[0], a2 = scr2[1];
        #pragma unroll
        for (int i = 1; i < NT / 32; i++) {
            int b1 = scr2[i * 2], b2 = scr2[i * 2 + 1];
            int n1 = min(a1, b1);
            int n2 = min(max(a1, b1), min(a2, b2));
            a1 = n1; a2 = n2;
        }
        scr2[0] = a1; scr2[1] = a2;
    }
    __syncthreads();
    s1 = scr2[0]; s2 = scr2[1];
    __syncthreads();
}

// ---------------- complex helpers -------------------------------------------
__device__ __forceinline__ float2 cadd(float2 a, float2 b) { return make_float2(a.x + b.x, a.y + b.y); }
__device__ __forceinline__ float2 csub(float2 a, float2 b) { return make_float2(a.x - b.x, a.y - b.y); }
__device__ __forceinline__ float2 cmul(float2 a, float2 b) {
    return make_float2(a.x * b.x - a.y * b.y, a.x * b.y + a.y * b.x);
}

// one radix-8 DIF butterfly at 'base' with stride S; tw1 = first twiddle.
template<int S, bool TW>
__device__ __forceinline__ void bfly8(float2* __restrict__ z, int base, float2 tw1) {
    float2 x0 = z[POFF(base + 0 * S)];
    float2 x1 = z[POFF(base + 1 * S)];
    float2 x2 = z[POFF(base + 2 * S)];
    float2 x3 = z[POFF(base + 3 * S)];
    float2 x4 = z[POFF(base + 4 * S)];
    float2 x5 = z[POFF(base + 5 * S)];
    float2 x6 = z[POFF(base + 6 * S)];
    float2 x7 = z[POFF(base + 7 * S)];

    float2 t0 = cadd(x0, x4), t4 = csub(x0, x4);
    float2 t1 = cadd(x1, x5), t5 = csub(x1, x5);
    float2 t2 = cadd(x2, x6), t6 = csub(x2, x6);
    float2 t3 = cadd(x3, x7), t7 = csub(x3, x7);

    float2 u0 = cadd(t0, t2), u2 = csub(t0, t2);
    float2 u1 = cadd(t1, t3), u3 = csub(t1, t3);
    float2 y0 = cadd(u0, u1);
    float2 y4 = csub(u0, u1);
    float2 y2 = make_float2(u2.x + u3.y, u2.y - u3.x);
    float2 y6 = make_float2(u2.x - u3.y, u2.y + u3.x);

    float2 w0 = t4;
    float2 w1 = make_float2(C8 * (t5.x + t5.y), C8 * (t5.y - t5.x));
    float2 w2 = make_float2(t6.y, -t6.x);
    float2 w3 = make_float2(C8 * (t7.y - t7.x), -C8 * (t7.x + t7.y));
    float2 p0 = cadd(w0, w2), p2 = csub(w0, w2);
    float2 p1 = cadd(w1, w3), p3 = csub(w1, w3);
    float2 y1 = cadd(p0, p1);
    float2 y5 = csub(p0, p1);
    float2 y3 = make_float2(p2.x + p3.y, p2.y - p3.x);
    float2 y7 = make_float2(p2.x - p3.y, p2.y + p3.x);

    if (TW) {
        float2 tw2 = cmul(tw1, tw1);
        float2 tw3 = cmul(tw2, tw1);
        float2 tw4 = cmul(tw2, tw2);
        float2 tw5 = cmul(tw3, tw2);
        float2 tw6 = cmul(tw3, tw3);
        float2 tw7 = cmul(tw4, tw3);
        y1 = cmul(y1, tw1);
        y2 = cmul(y2, tw2);
        y3 = cmul(y3, tw3);
        y4 = cmul(y4, tw4);
        y5 = cmul(y5, tw5);
        y6 = cmul(y6, tw6);
        y7 = cmul(y7, tw7);
    }

    z[POFF(base + 0 * S)] = y0;
    z[POFF(base + 1 * S)] = y1;
    z[POFF(base + 2 * S)] = y2;
    z[POFF(base + 3 * S)] = y3;
    z[POFF(base + 4 * S)] = y4;
    z[POFF(base + 5 * S)] = y5;
    z[POFF(base + 6 * S)] = y6;
    z[POFF(base + 7 * S)] = y7;
}

// octal digit reverse of 12-bit index
__device__ __forceinline__ int drev(int k) {
    return ((k & 7) << 9) | (((k >> 3) & 7) << 6) | (((k >> 6) & 7) << 3) | ((k >> 9) & 7);
}

// ---------------- main kernel: one CTA per row -------------------------------
__global__ __launch_bounds__(NT, 4)
void feat_kernel(const float* __restrict__ xin, float* __restrict__ out, int nrows) {
    extern __shared__ float smf[];           // SMEM_F2 float2 = 36864 B
    float2* z = (float2*)smf;

    int row = blockIdx.x;
    if (row >= nrows) return;
    const float4* x4 = (const float4*)(xin + (size_t)row * N);
    int tid = threadIdx.x;

    // ---- pass 1: vectorized load + max/min/sum/sumsq --------------------
    float mx = -3.4e38f, mn = 3.4e38f, s = 0.f, s2 = 0.f;
    #pragma unroll
    for (int rep = 0; rep < N / 4 / NT; rep++) {     // 8 float4 per thread
        int j = tid + rep * NT;
        float4 v = x4[j];
        int n = 2 * j;
        z[POFF(n)]     = make_float2(v.x, v.y);
        z[POFF(n + 1)] = make_float2(v.z, v.w);
        mx = fmaxf(fmaxf(mx, v.x), fmaxf(v.y, fmaxf(v.z, v.w)));
        mn = fminf(fminf(mn, v.x), fminf(v.y, fminf(v.z, v.w)));
        s  += (v.x + v.y) + (v.z + v.w);
        s2 += (v.x * v.x + v.y * v.y) + (v.z * v.z + v.w * v.w);
    }
    __syncthreads();
    mx = bredMaxF(mx);
    mn = bredMinF(mn);
    s  = bredSumF(s);
    s2 = bredSumF(s2);

    // ---- pass 2: peaks/valleys + first-two valleys (fused) ----------------
    int cnt = 0;                 // npk + (nvl<<16)
    int p0 = N, vs1 = N, vs2 = N, vlast = -1;
    #pragma unroll
    for (int rep = 0; rep < M / NT; rep++) {
        int n = tid + rep * NT;
        float2 zc = z[POFF(n)];
        // element i = 2n (needs left neighbor from pair n-1)
        if (n > 0) {
            float l = z[POFF(n - 1)].y;
            float c = zc.x, r = zc.y;
            int i = 2 * n;
            if (c > l && c > r) { cnt += 1; p0 = min(p0, i); }
            if (c < l && c < r) {
                cnt += (1 << 16);
                if (vs1 == N) vs1 = i; else if (vs2 == N) vs2 = i;
                vlast = max(vlast, i);
            }
        }
        // element i = 2n+1 (needs right neighbor from pair n+1)
        if (n < M - 1) {
            float r = z[POFF(n + 1)].x;
            float l = zc.x, c = zc.y;
            int i = 2 * n + 1;
            if (c > l && c > r) { cnt += 1; p0 = min(p0, i); }
            if (c < l && c < r) {
                cnt += (1 << 16);
                if (vs1 == N) vs1 = i; else if (vs2 == N) vs2 = i;
                vlast = max(vlast, i);
            }
        }
    }
    cnt   = bredSumI(cnt);
    p0    = bredMinI(p0);
    vlast = bredMaxI(vlast);
    bredMin2I(vs1, vs2);
    int npk = cnt & 0xffff, nvl = cnt >> 16;
    int v0 = vs1, v1 = vs2;

    bool valid = (npk >= 1) && (nvl >= 2);
    float PA = 0.f, A2 = 0.f, A1 = 0.f, PH = 0.f, PWHH = 0.f;

    if (valid) {
        float sp0 = smf[XIDX(p0)];
        float sv0 = smf[XIDX(v0)];
        PH = sp0 - sv0;
        float hh = (sp0 + sv0) * 0.5f;

        // ---- pass 3: trapezoid sums + half-height indices ----------------
        float pa = 0.f, a2 = 0.f, a1 = 0.f;
        int li = N, ri = -1;
        #pragma unroll
        for (int rep = 0; rep < M / NT; rep++) {
            int n = tid + rep * NT;
            float2 zc = z[POFF(n)];
            float rn = (n < M - 1) ? z[POFF(n + 1)].x : 0.f;
            // element i = 2n : seg = (zc.x + zc.y)
            {
                int i = 2 * n;
                float seg = (zc.x + zc.y) * (0.5f / SRf);
                if (i >= v0 && i <= vlast - 2) pa += seg;
                if (i >= p0 && i <= v1 - 2)    a2 += seg;
                if (i >= v0 && i <= p0 - 2)    a1 += seg;
                if (zc.x >= hh) {
                    if (i >= v0 && i < p0)  li = min(li, i);
                    if (i > v0 && i <= p0)  ri = max(ri, i);
                }
            }
            // element i = 2n+1 : seg = (zc.y + rn), skip at i == N-1
            {
                int i = 2 * n + 1;
                if (i < N - 1) {
                    float seg = (zc.y + rn) * (0.5f / SRf);
                    if (i >= v0 && i <= vlast - 2) pa += seg;
                    if (i >= p0 && i <= v1 - 2)    a2 += seg;
                    if (i >= v0 && i <= p0 - 2)    a1 += seg;
                }
                if (zc.y >= hh) {
                    if (i >= v0 && i < p0)  li = min(li, i);
                    if (i > v0 && i <= p0)  ri = max(ri, i);
                }
            }
        }
        PA = bredSumF(pa);
        A2 = bredSumF(a2);
        A1 = bredSumF(a1);
        li = bredMinI(li);
        ri = bredMaxI(ri);
        if (li == N)  li = v0;
        if (ri == -1) ri = p0;
        PWHH = (float)(ri - li) / SRf;
    }
    __syncthreads();

    // ---- FFT: z[n] = x[2n] + i x[2n+1], 4096-pt, 4 radix-8 DIF passes ----
    // pass 1: L=4096, S=512; rep1 twiddle = rep0 twiddle * exp(-i*pi/8)
    {
        float sn, cs;
        __sincosf(-2.0f * PI_F * (float)tid / 4096.0f, &sn, &cs);
        float2 tw = make_float2(cs, sn);
        bfly8<512, true>(z, tid, tw);
        const float2 wstep = make_float2(0.92387953251128674f, -0.38268343236508978f);
        float2 twb = cmul(tw, wstep);
        bfly8<512, true>(z, tid + 256, twb);
    }
    __syncthreads();
    // pass 2: L=512, S=64; both reps share t = tid & 63
    {
        int t = tid & 63;
        float sn, cs;
        __sincosf(-2.0f * PI_F * (float)t / 512.0f, &sn, &cs);
        float2 tw = make_float2(cs, sn);
        bfly8<64, true>(z, (tid >> 6) * 512 + t, tw);
        bfly8<64, true>(z, ((tid + 256) >> 6) * 512 + t, tw);
    }
    __syncthreads();
    // pass 3: L=64, S=8; both reps share t = tid & 7
    {
        int t = tid & 7;
        float sn, cs;
        __sincosf(-2.0f * PI_F * (float)t / 64.0f, &sn, &cs);
        float2 tw = make_float2(cs, sn);
        bfly8<8, true>(z, (tid >> 3) * 64 + t, tw);
        bfly8<8, true>(z, ((tid + 256) >> 3) * 64 + t, tw);
    }
    __syncthreads();
    // pass 4: L=8, S=1, twiddle-free
    {
        float2 dummy = make_float2(1.f, 0.f);
        bfly8<1, false>(z, tid * 8, dummy);
        bfly8<1, false>(z, (tid + 256) * 8, dummy);
    }
    __syncthreads();

    // ---- unpack real FFT + magnitude sum ---------------------------------
    // X[k] = Ze + W^k Zo, X[k+M] = Ze - W^k Zo ; W^k recurrence by exp(-i*pi/16)
    float fs = 0.f;
    float2 Wk;
    {
        float sn, cs;
        __sincosf(-PI_F * (float)tid / (float)M, &sn, &cs);
        Wk = make_float2(cs, sn);
    }
    const float2 Wstep = make_float2(0.98078528040323043f, -0.19509032201612825f);
    #pragma unroll
    for (int rep = 0; rep < M / NT; rep++) {
        int k  = tid + rep * NT;
        int km = (M - k) & (M - 1);
        float2 Zk = z[POFF(drev(k))];
        float2 Zm = z[POFF(drev(km))];
        float2 Ze = make_float2(0.5f * (Zk.x + Zm.x), 0.5f * (Zk.y - Zm.y));
        float2 Bv = make_float2(0.5f * (Zk.x - Zm.x), 0.5f * (Zk.y + Zm.y));
        float2 Zo = make_float2(Bv.y, -Bv.x);
        float2 WZo = cmul(Wk, Zo);
        float ax = Ze.x + WZo.x, ay = Ze.y + WZo.y;
        float bx = Ze.x - WZo.x, by = Ze.y - WZo.y;
        fs += fsqrt_ap(ax * ax + ay * ay) + fsqrt_ap(bx * bx + by * by);
        Wk = cmul(Wk, Wstep);
    }
    fs = bredSumF(fs);
    float fftm = fs * (1.0f / (float)N);

    // ---- write output ----------------------------------------------------
    if (tid == 0) {
        float mean = s * (1.0f / (float)N);
        float var  = (s2 - s * mean) * (1.0f / (float)(N - 1));
        float sd   = sqrtf(var);
        float* o = out + (size_t)row * 10;
        o[0] = mx;
        o[1] = mx - mn;
        o[2] = var;
        o[3] = sd;
        o[4] = fftm;
        o[5] = valid ? PA : 0.f;
        o[6] = valid ? A2 : 0.f;
        o[7] = valid ? PH : 0.f;
        o[8] = valid ? A1 : 0.f;
        o[9] = valid ? PWHH : 0.f;
    }
}

extern "C" void kernel_launch(void* const* d_in, const int* in_sizes, int n_in,
                              void* d_out, int out_size) {
    const float* x = (const float*)d_in[0];
    float* out = (float*)d_out;
    int nrows = in_sizes[0] / N;  // 2048
    size_t smem_bytes = (size_t)SMEM_F2 * sizeof(float2);  // 36864 B
    cudaFuncSetAttribute(feat_kernel, cudaFuncAttributeMaxDynamicSharedMemorySize,
                         (int)smem_bytes);
    feat_kernel<<<nrows, NT, smem_bytes>>>(x, out, nrows);
}

// round 11
// speedup vs baseline: 4.9743x; 1.2541x over previous
#include <cuda_runtime.h>
#include <math.h>

#define N     8192          // real signal length
#define M     4096          // packed complex length
#define NT    256
#define SRf   30.0f
#define PI_F  3.14159265358979f
#define C8    0.70710678118654752f   // sqrt(2)/2

// padded complex offset: one extra float2 per 8 -> conflict-free pass strides
#define POFF(n)  ((n) + ((n) >> 3))
// scalar view of x[i] inside the padded complex buffer (z[n].x=x[2n], .y=x[2n+1])
#define XIDX(i)  (((((i) >> 1) + ((i) >> 4)) << 1) | ((i) & 1))

#define SMEM_F2  (M + M / 8)         // 4608 float2 = 36864 B

__device__ __forceinline__ float fsqrt_ap(float x) {
    float r; asm("sqrt.approx.f32 %0, %1;" : "=f"(r) : "f"(x)); return r;
}

// ---------------- block reductions (deterministic) ---------------------------
__device__ __forceinline__ float bredSumF(float v) {
    __shared__ float scr[8];
    int lane = threadIdx.x & 31, w = threadIdx.x >> 5;
    #pragma unroll
    for (int o = 16; o; o >>= 1) v += __shfl_down_sync(0xffffffffu, v, o);
    __syncthreads();
    if (lane == 0) scr[w] = v;
    __syncthreads();
    if (threadIdx.x == 0) {
        float r = scr[0];
        #pragma unroll
        for (int i = 1; i < NT / 32; i++) r += scr[i];
        scr[0] = r;
    }
    __syncthreads();
    v = scr[0];
    __syncthreads();
    return v;
}
__device__ __forceinline__ float bredMaxF(float v) {
    __shared__ float scr[8];
    int lane = threadIdx.x & 31, w = threadIdx.x >> 5;
    #pragma unroll
    for (int o = 16; o; o >>= 1) v = fmaxf(v, __shfl_down_sync(0xffffffffu, v, o));
    __syncthreads();
    if (lane == 0) scr[w] = v;
    __syncthreads();
    if (threadIdx.x == 0) {
        float r = scr[0];
        #pragma unroll
        for (int i = 1; i < NT / 32; i++) r = fmaxf(r, scr[i]);
        scr[0] = r;
    }
    __syncthreads();
    v = scr[0];
    __syncthreads();
    return v;
}
__device__ __forceinline__ float bredMinF(float v) {
    __shared__ float scr[8];
    int lane = threadIdx.x & 31, w = threadIdx.x >> 5;
    #pragma unroll
    for (int o = 16; o; o >>= 1) v = fminf(v, __shfl_down_sync(0xffffffffu, v, o));
    __syncthreads();
    if (lane == 0) scr[w] = v;
    __syncthreads();
    if (threadIdx.x == 0) {
        float r = scr[0];
        #pragma unroll
        for (int i = 1; i < NT / 32; i++) r = fminf(r, scr[i]);
        scr[0] = r;
    }
    __syncthreads();
    v = scr[0];
    __syncthreads();
    return v;
}
__device__ __forceinline__ int bredSumI(int v) {
    __shared__ int scr[8];
    int lane = threadIdx.x & 31, w = threadIdx.x >> 5;
    #pragma unroll
    for (int o = 16; o; o >>= 1) v += __shfl_down_sync(0xffffffffu, v, o);
    __syncthreads();
    if (lane == 0) scr[w] = v;
    __syncthreads();
    if (threadIdx.x == 0) {
        int r = scr[0];
        #pragma unroll
        for (int i = 1; i < NT / 32; i++) r += scr[i];
        scr[0] = r;
    }
    __syncthreads();
    v = scr[0];
    __syncthreads();
    return v;
}
__device__ __forceinline__ int bredMinI(int v) {
    __shared__ int scr[8];
    int lane = threadIdx.x & 31, w = threadIdx.x >> 5;
    #pragma unroll
    for (int o = 16; o; o >>= 1) v = min(v, __shfl_down_sync(0xffffffffu, v, o));
    __syncthreads();
    if (lane == 0) scr[w] = v;
    __syncthreads();
    if (threadIdx.x == 0) {
        int r = scr[0];
        #pragma unroll
        for (int i = 1; i < NT / 32; i++) r = min(r, scr[i]);
        scr[0] = r;
    }
    __syncthreads();
    v = scr[0];
    __syncthreads();
    return v;
}
__device__ __forceinline__ int bredMaxI(int v) {
    __shared__ int scr[8];
    int lane = threadIdx.x & 31, w = threadIdx.x >> 5;
    #pragma unroll
    for (int o = 16; o; o >>= 1) v = max(v, __shfl_down_sync(0xffffffffu, v, o));
    __syncthreads();
    if (lane == 0) scr[w] = v;
    __syncthreads();
    if (threadIdx.x == 0) {
        int r = scr[0];
        #pragma unroll
        for (int i = 1; i < NT / 32; i++) r = max(r, scr[i]);
        scr[0] = r;
    }
    __syncthreads();
    v = scr[0];
    __syncthreads();
    return v;
}
// two smallest values across block (s1 <= s2 per thread on entry)
__device__ __forceinline__ void bredMin2I(int& s1, int& s2) {
    __shared__ int scr2[16];
    int lane = threadIdx.x & 31, w = threadIdx.x >> 5;
    #pragma unroll
    for (int o = 16; o; o >>= 1) {
        int o1 = __shfl_down_sync(0xffffffffu, s1, o);
        int o2 = __shfl_down_sync(0xffffffffu, s2, o);
        int n1 = min(s1, o1);
        int n2 = min(max(s1, o1), min(s2, o2));
        s1 = n1; s2 = n2;
    }
    __syncthreads();
    if (lane == 0) { scr2[w * 2] = s1; scr2[w * 2 + 1] = s2; }
    __syncthreads();
    if (threadIdx.x == 0) {
        int a1 = scr2[0], a2 = scr2[1];
        #pragma unroll
        for (int i = 1; i < NT / 32; i++) {
            int b1 = scr2[i * 2], b2 = scr2[i * 2 + 1];
            int n1 = min(a1, b1);
            int n2 = min(max(a1, b1), min(a2, b2));
            a1 = n1; a2 = n2;
        }
        scr2[0] = a1; scr2[1] = a2;
    }
    __syncthreads();
    s1 = scr2[0]; s2 = scr2[1];
    __syncthreads();
}

// ---------------- complex helpers -------------------------------------------
__device__ __forceinline__ float2 cadd(float2 a, float2 b) { return make_float2(a.x + b.x, a.y + b.y); }
__device__ __forceinline__ float2 csub(float2 a, float2 b) { return make_float2(a.x - b.x, a.y - b.y); }
__device__ __forceinline__ float2 cmul(float2 a, float2 b) {
    return make_float2(a.x * b.x - a.y * b.y, a.x * b.y + a.y * b.x);
}

// one radix-8 DIF butterfly at 'base' with stride S; tw1 = first twiddle.
template<int S, bool TW>
__device__ __forceinline__ void bfly8(float2* __restrict__ z, int base, float2 tw1) {
    float2 x0 = z[POFF(base + 0 * S)];
    float2 x1 = z[POFF(base + 1 * S)];
    float2 x2 = z[POFF(base + 2 * S)];
    float2 x3 = z[POFF(base + 3 * S)];
    float2 x4 = z[POFF(base + 4 * S)];
    float2 x5 = z[POFF(base + 5 * S)];
    float2 x6 = z[POFF(base + 6 * S)];
    float2 x7 = z[POFF(base + 7 * S)];

    float2 t0 = cadd(x0, x4), t4 = csub(x0, x4);
    float2 t1 = cadd(x1, x5), t5 = csub(x1, x5);
    float2 t2 = cadd(x2, x6), t6 = csub(x2, x6);
    float2 t3 = cadd(x3, x7), t7 = csub(x3, x7);

    float2 u0 = cadd(t0, t2), u2 = csub(t0, t2);
    float2 u1 = cadd(t1, t3), u3 = csub(t1, t3);
    float2 y0 = cadd(u0, u1);
    float2 y4 = csub(u0, u1);
    float2 y2 = make_float2(u2.x + u3.y, u2.y - u3.x);
    float2 y6 = make_float2(u2.x - u3.y, u2.y + u3.x);

    float2 w0 = t4;
    float2 w1 = make_float2(C8 * (t5.x + t5.y), C8 * (t5.y - t5.x));
    float2 w2 = make_float2(t6.y, -t6.x);
    float2 w3 = make_float2(C8 * (t7.y - t7.x), -C8 * (t7.x + t7.y));
    float2 p0 = cadd(w0, w2), p2 = csub(w0, w2);
    float2 p1 = cadd(w1, w3), p3 = csub(w1, w3);
    float2 y1 = cadd(p0, p1);
    float2 y5 = csub(p0, p1);
    float2 y3 = make_float2(p2.x + p3.y, p2.y - p3.x);
    float2 y7 = make_float2(p2.x - p3.y, p2.y + p3.x);

    if (TW) {
        float2 tw2 = cmul(tw1, tw1);
        float2 tw3 = cmul(tw2, tw1);
        float2 tw4 = cmul(tw2, tw2);
        float2 tw5 = cmul(tw3, tw2);
        float2 tw6 = cmul(tw3, tw3);
        float2 tw7 = cmul(tw4, tw3);
        y1 = cmul(y1, tw1);
        y2 = cmul(y2, tw2);
        y3 = cmul(y3, tw3);
        y4 = cmul(y4, tw4);
        y5 = cmul(y5, tw5);
        y6 = cmul(y6, tw6);
        y7 = cmul(y7, tw7);
    }

    z[POFF(base + 0 * S)] = y0;
    z[POFF(base + 1 * S)] = y1;
    z[POFF(base + 2 * S)] = y2;
    z[POFF(base + 3 * S)] = y3;
    z[POFF(base + 4 * S)] = y4;
    z[POFF(base + 5 * S)] = y5;
    z[POFF(base + 6 * S)] = y6;
    z[POFF(base + 7 * S)] = y7;
}

// octal digit reverse of 12-bit index
__device__ __forceinline__ int drev(int k) {
    return ((k & 7) << 9) | (((k >> 3) & 7) << 6) | (((k >> 6) & 7) << 3) | ((k >> 9) & 7);
}

// ---------------- main kernel: one CTA per row -------------------------------
__global__ __launch_bounds__(NT, 4)
void feat_kernel(const float* __restrict__ xin, float* __restrict__ out, int nrows) {
    extern __shared__ float smf[];           // SMEM_F2 float2 = 36864 B
    float2* z = (float2*)smf;

    int row = blockIdx.x;
    if (row >= nrows) return;
    const float4* x4 = (const float4*)(xin + (size_t)row * N);
    int tid  = threadIdx.x;
    int lane = tid & 31;
    int wrp  = tid >> 5;

    // ---- pass 1: vectorized load + max/min/sum/sumsq --------------------
    float mx = -3.4e38f, mn = 3.4e38f, s = 0.f, s2 = 0.f;
    #pragma unroll
    for (int rep = 0; rep < N / 4 / NT; rep++) {     // 8 float4 per thread
        int j = tid + rep * NT;
        float4 v = x4[j];
        int n = 2 * j;
        z[POFF(n)]     = make_float2(v.x, v.y);
        z[POFF(n + 1)] = make_float2(v.z, v.w);
        mx = fmaxf(fmaxf(mx, v.x), fmaxf(v.y, fmaxf(v.z, v.w)));
        mn = fminf(fminf(mn, v.x), fminf(v.y, fminf(v.z, v.w)));
        s  += (v.x + v.y) + (v.z + v.w);
        s2 += (v.x * v.x + v.y * v.y) + (v.z * v.z + v.w * v.w);
    }
    __syncthreads();
    mx = bredMaxF(mx);
    mn = bredMinF(mn);
    s  = bredSumF(s);
    s2 = bredSumF(s2);

    // ---- pass 2: peaks/valleys + first-two valleys (fused) ----------------
    int cnt = 0;                 // npk + (nvl<<16)
    int p0 = N, vs1 = N, vs2 = N, vlast = -1;
    #pragma unroll
    for (int rep = 0; rep < M / NT; rep++) {
        int n = tid + rep * NT;
        float2 zc = z[POFF(n)];
        // element i = 2n (needs left neighbor from pair n-1)
        if (n > 0) {
            float l = z[POFF(n - 1)].y;
            float c = zc.x, r = zc.y;
            int i = 2 * n;
            if (c > l && c > r) { cnt += 1; p0 = min(p0, i); }
            if (c < l && c < r) {
                cnt += (1 << 16);
                if (vs1 == N) vs1 = i; else if (vs2 == N) vs2 = i;
                vlast = max(vlast, i);
            }
        }
        // element i = 2n+1 (needs right neighbor from pair n+1)
        if (n < M - 1) {
            float r = z[POFF(n + 1)].x;
            float l = zc.x, c = zc.y;
            int i = 2 * n + 1;
            if (c > l && c > r) { cnt += 1; p0 = min(p0, i); }
            if (c < l && c < r) {
                cnt += (1 << 16);
                if (vs1 == N) vs1 = i; else if (vs2 == N) vs2 = i;
                vlast = max(vlast, i);
            }
        }
    }
    cnt   = bredSumI(cnt);
    p0    = bredMinI(p0);
    vlast = bredMaxI(vlast);
    bredMin2I(vs1, vs2);
    int npk = cnt & 0xffff, nvl = cnt >> 16;
    int v0 = vs1, v1 = vs2;

    bool valid = (npk >= 1) && (nvl >= 2);
    float PA = 0.f, A2 = 0.f, A1 = 0.f, PH = 0.f, PWHH = 0.f;

    if (valid) {
        float sp0 = smf[XIDX(p0)];
        float sv0 = smf[XIDX(v0)];
        PH = sp0 - sv0;
        float hh = (sp0 + sv0) * 0.5f;

        // ---- pass 3: trapezoid sums + half-height indices ----------------
        float pa = 0.f, a2 = 0.f, a1 = 0.f;
        int li = N, ri = -1;
        #pragma unroll
        for (int rep = 0; rep < M / NT; rep++) {
            int n = tid + rep * NT;
            float2 zc = z[POFF(n)];
            float rn = (n < M - 1) ? z[POFF(n + 1)].x : 0.f;
            // element i = 2n : seg = (zc.x + zc.y)
            {
                int i = 2 * n;
                float seg = (zc.x + zc.y) * (0.5f / SRf);
                if (i >= v0 && i <= vlast - 2) pa += seg;
                if (i >= p0 && i <= v1 - 2)    a2 += seg;
                if (i >= v0 && i <= p0 - 2)    a1 += seg;
                if (zc.x >= hh) {
                    if (i >= v0 && i < p0)  li = min(li, i);
                    if (i > v0 && i <= p0)  ri = max(ri, i);
                }
            }
            // element i = 2n+1 : seg = (zc.y + rn), skip at i == N-1
            {
                int i = 2 * n + 1;
                if (i < N - 1) {
                    float seg = (zc.y + rn) * (0.5f / SRf);
                    if (i >= v0 && i <= vlast - 2) pa += seg;
                    if (i >= p0 && i <= v1 - 2)    a2 += seg;
                    if (i >= v0 && i <= p0 - 2)    a1 += seg;
                }
                if (zc.y >= hh) {
                    if (i >= v0 && i < p0)  li = min(li, i);
                    if (i > v0 && i <= p0)  ri = max(ri, i);
                }
            }
        }
        PA = bredSumF(pa);
        A2 = bredSumF(a2);
        A1 = bredSumF(a1);
        li = bredMinI(li);
        ri = bredMaxI(ri);
        if (li == N)  li = v0;
        if (ri == -1) ri = p0;
        PWHH = (float)(ri - li) / SRf;
    }
    __syncthreads();

    // ---- FFT: z[n] = x[2n] + i x[2n+1], 4096-pt, 4 radix-8 DIF passes ----
    // pass 1: L=4096, S=512; rep1 twiddle = rep0 twiddle * exp(-i*pi/8)
    {
        float sn, cs;
        __sincosf(-2.0f * PI_F * (float)tid / 4096.0f, &sn, &cs);
        float2 tw = make_float2(cs, sn);
        bfly8<512, true>(z, tid, tw);
        const float2 wstep = make_float2(0.92387953251128674f, -0.38268343236508978f);
        float2 twb = cmul(tw, wstep);
        bfly8<512, true>(z, tid + 256, twb);
    }
    __syncthreads();
    // pass 2: L=512, S=64; both reps share t = tid & 63
    {
        int t = tid & 63;
        float sn, cs;
        __sincosf(-2.0f * PI_F * (float)t / 512.0f, &sn, &cs);
        float2 tw = make_float2(cs, sn);
        bfly8<64, true>(z, (tid >> 6) * 512 + t, tw);
        bfly8<64, true>(z, ((tid + 256) >> 6) * 512 + t, tw);
    }
    __syncthreads();
    // pass 3: L=64, S=8; both reps share t = tid & 7
    {
        int t = tid & 7;
        float sn, cs;
        __sincosf(-2.0f * PI_F * (float)t / 64.0f, &sn, &cs);
        float2 tw = make_float2(cs, sn);
        bfly8<8, true>(z, (tid >> 3) * 64 + t, tw);
        bfly8<8, true>(z, ((tid + 256) >> 3) * 64 + t, tw);
    }
    __syncthreads();
    // pass 4: L=8, S=1, twiddle-free
    {
        float2 dummy = make_float2(1.f, 0.f);
        bfly8<1, false>(z, tid * 8, dummy);
        bfly8<1, false>(z, (tid + 256) * 8, dummy);
    }
    __syncthreads();

    // ---- unpack real FFT + magnitude sum (halved via conjugate symmetry) --
    // total = (a0+b0) + 2*sum_{k=1..2047}(a_k+b_k) + 2*|X[2048]|,
    //   a_k = |X[k]| = |Ze + W^k Zo|, b_k = |X[k+M]| = |Ze - W^k Zo|.
    // Lane->k map k = lane*64 + wrp + 8*rep puts lane bits in k's HIGH octal
    // digits, so drev(k) varies in LOW digits across a warp -> ~2-way (floor).
    float fs = 0.f;
    {
        int k0 = lane * 64 + wrp;
        float2 Wk;
        {
            float sn, cs;
            __sincosf(-PI_F * (float)k0 / (float)M, &sn, &cs);
            Wk = make_float2(cs, sn);
        }
        // step = exp(-i*pi*8/4096) = exp(-i*pi/512)
        const float2 Wstep = make_float2(0.99998117528260111f, -0.0061358846491544753f);
        #pragma unroll
        for (int rep = 0; rep < 8; rep++) {
            int k  = k0 + 8 * rep;
            int km = (M - k) & (M - 1);
            float2 Zk = z[POFF(drev(k))];
            float2 Zm = z[POFF(drev(km))];
            float2 Ze = make_float2(0.5f * (Zk.x + Zm.x), 0.5f * (Zk.y - Zm.y));
            float2 Bv = make_float2(0.5f * (Zk.x - Zm.x), 0.5f * (Zk.y + Zm.y));
            float2 Zo = make_float2(Bv.y, -Bv.x);
            float2 WZo = cmul(Wk, Zo);
            float ax = Ze.x + WZo.x, ay = Ze.y + WZo.y;
            float bx = Ze.x - WZo.x, by = Ze.y - WZo.y;
            float mag = fsqrt_ap(ax * ax + ay * ay) + fsqrt_ap(bx * bx + by * by);
            fs += (k == 0) ? mag : 2.0f * mag;
            Wk = cmul(Wk, Wstep);
        }
        if (tid == 0) {
            // k = 2048 term: X[2048] = (Zk.x, -Zk.y) at storage drev(2048) = 4
            float2 Zk = z[POFF(4)];
            fs += 2.0f * fsqrt_ap(Zk.x * Zk.x + Zk.y * Zk.y);
        }
    }
    fs = bredSumF(fs);
    float fftm = fs * (1.0f / (float)N);

    // ---- write output ----------------------------------------------------
    if (tid == 0) {
        float mean = s * (1.0f / (float)N);
        float var  = (s2 - s * mean) * (1.0f / (float)(N - 1));
        float sd   = sqrtf(var);
        float* o = out + (size_t)row * 10;
        o[0] = mx;
        o[1] = mx - mn;
        o[2] = var;
        o[3] = sd;
        o[4] = fftm;
        o[5] = valid ? PA : 0.f;
        o[6] = valid ? A2 : 0.f;
        o[7] = valid ? PH : 0.f;
        o[8] = valid ? A1 : 0.f;
        o[9] = valid ? PWHH : 0.f;
    }
}

extern "C" void kernel_launch(void* const* d_in, const int* in_sizes, int n_in,
                              void* d_out, int out_size) {
    const float* x = (const float*)d_in[0];
    float* out = (float*)d_out;
    int nrows = in_sizes[0] / N;  // 2048
    size_t smem_bytes = (size_t)SMEM_F2 * sizeof(float2);  // 36864 B
    cudaFuncSetAttribute(feat_kernel, cudaFuncAttributeMaxDynamicSharedMemorySize,
                         (int)smem_bytes);
    feat_kernel<<<nrows, NT, smem_bytes>>>(x, out, nrows);
}

// round 12
// speedup vs baseline: 5.7071x; 1.1473x over previous
#include <cuda_runtime.h>
#include <math.h>

#define N     8192          // real signal length
#define M     4096          // packed complex length
#define NT    256
#define SRf   30.0f
#define PI_F  3.14159265358979f
#define C8    0.70710678118654752f   // sqrt(2)/2

// padded complex offset: one extra float2 per 8 -> conflict-free pass strides
#define POFF(n)  ((n) + ((n) >> 3))
// scalar view of x[i] inside the padded complex buffer (z[n].x=x[2n], .y=x[2n+1])
#define XIDX(i)  (((((i) >> 1) + ((i) >> 4)) << 1) | ((i) & 1))

#define SMEM_F2  (M + M / 8)         // 4608 float2 = 36864 B

__device__ __forceinline__ float fsqrt_ap(float x) {
    float r; asm("sqrt.approx.f32 %0, %1;" : "=f"(r) : "f"(x)); return r;
}

// ---------------- block reductions (deterministic) ---------------------------
__device__ __forceinline__ float bredSumF(float v) {
    __shared__ float scr[8];
    int lane = threadIdx.x & 31, w = threadIdx.x >> 5;
    #pragma unroll
    for (int o = 16; o; o >>= 1) v += __shfl_down_sync(0xffffffffu, v, o);
    __syncthreads();
    if (lane == 0) scr[w] = v;
    __syncthreads();
    if (threadIdx.x == 0) {
        float r = scr[0];
        #pragma unroll
        for (int i = 1; i < NT / 32; i++) r += scr[i];
        scr[0] = r;
    }
    __syncthreads();
    v = scr[0];
    __syncthreads();
    return v;
}
__device__ __forceinline__ float bredMaxF(float v) {
    __shared__ float scr[8];
    int lane = threadIdx.x & 31, w = threadIdx.x >> 5;
    #pragma unroll
    for (int o = 16; o; o >>= 1) v = fmaxf(v, __shfl_down_sync(0xffffffffu, v, o));
    __syncthreads();
    if (lane == 0) scr[w] = v;
    __syncthreads();
    if (threadIdx.x == 0) {
        float r = scr[0];
        #pragma unroll
        for (int i = 1; i < NT / 32; i++) r = fmaxf(r, scr[i]);
        scr[0] = r;
    }
    __syncthreads();
    v = scr[0];
    __syncthreads();
    return v;
}
__device__ __forceinline__ float bredMinF(float v) {
    __shared__ float scr[8];
    int lane = threadIdx.x & 31, w = threadIdx.x >> 5;
    #pragma unroll
    for (int o = 16; o; o >>= 1) v = fminf(v, __shfl_down_sync(0xffffffffu, v, o));
    __syncthreads();
    if (lane == 0) scr[w] = v;
    __syncthreads();
    if (threadIdx.x == 0) {
        float r = scr[0];
        #pragma unroll
        for (int i = 1; i < NT / 32; i++) r = fminf(r, scr[i]);
        scr[0] = r;
    }
    __syncthreads();
    v = scr[0];
    __syncthreads();
    return v;
}
__device__ __forceinline__ int bredSumI(int v) {
    __shared__ int scr[8];
    int lane = threadIdx.x & 31, w = threadIdx.x >> 5;
    #pragma unroll
    for (int o = 16; o; o >>= 1) v += __shfl_down_sync(0xffffffffu, v, o);
    __syncthreads();
    if (lane == 0) scr[w] = v;
    __syncthreads();
    if (threadIdx.x == 0) {
        int r = scr[0];
        #pragma unroll
        for (int i = 1; i < NT / 32; i++) r += scr[i];
        scr[0] = r;
    }
    __syncthreads();
    v = scr[0];
    __syncthreads();
    return v;
}
__device__ __forceinline__ int bredMinI(int v) {
    __shared__ int scr[8];
    int lane = threadIdx.x & 31, w = threadIdx.x >> 5;
    #pragma unroll
    for (int o = 16; o; o >>= 1) v = min(v, __shfl_down_sync(0xffffffffu, v, o));
    __syncthreads();
    if (lane == 0) scr[w] = v;
    __syncthreads();
    if (threadIdx.x == 0) {
        int r = scr[0];
        #pragma unroll
        for (int i = 1; i < NT / 32; i++) r = min(r, scr[i]);
        scr[0] = r;
    }
    __syncthreads();
    v = scr[0];
    __syncthreads();
    return v;
}
__device__ __forceinline__ int bredMaxI(int v) {
    __shared__ int scr[8];
    int lane = threadIdx.x & 31, w = threadIdx.x >> 5;
    #pragma unroll
    for (int o = 16; o; o >>= 1) v = max(v, __shfl_down_sync(0xffffffffu, v, o));
    __syncthreads();
    if (lane == 0) scr[w] = v;
    __syncthreads();
    if (threadIdx.x == 0) {
        int r = scr[0];
        #pragma unroll
        for (int i = 1; i < NT / 32; i++) r = max(r, scr[i]);
        scr[0] = r;
    }
    __syncthreads();
    v = scr[0];
    __syncthreads();
    return v;
}
// two smallest values across block (s1 <= s2 per thread on entry)
__device__ __forceinline__ void bredMin2I(int& s1, int& s2) {
    __shared__ int scr2[16];
    int lane = threadIdx.x & 31, w = threadIdx.x >> 5;
    #pragma unroll
    for (int o = 16; o; o >>= 1) {
        int o1 = __shfl_down_sync(0xffffffffu, s1, o);
        int o2 = __shfl_down_sync(0xffffffffu, s2, o);
        int n1 = min(s1, o1);
        int n2 = min(max(s1, o1), min(s2, o2));
        s1 = n1; s2 = n2;
    }
    __syncthreads();
    if (lane == 0) { scr2[w * 2] = s1; scr2[w * 2 + 1] = s2; }
    __syncthreads();
    if (threadIdx.x == 0) {
        int a1 = scr2[0], a2 = scr2[1];
        #pragma unroll
        for (int i = 1; i < NT / 32; i++) {
            int b1 = scr2[i * 2], b2 = scr2[i * 2 + 1];
            int n1 = min(a1, b1);
            int n2 = min(max(a1, b1), min(a2, b2));
            a1 = n1; a2 = n2;
        }
        scr2[0] = a1; scr2[1] = a2;
    }
    __syncthreads();
    s1 = scr2[0]; s2 = scr2[1];
    __syncthreads();
}

// ---------------- complex helpers -------------------------------------------
__device__ __forceinline__ float2 cadd(float2 a, float2 b) { return make_float2(a.x + b.x, a.y + b.y); }
__device__ __forceinline__ float2 csub(float2 a, float2 b) { return make_float2(a.x - b.x, a.y - b.y); }
__device__ __forceinline__ float2 cmul(float2 a, float2 b) {
    return make_float2(a.x * b.x - a.y * b.y, a.x * b.y + a.y * b.x);
}

// one radix-8 DIF butterfly at 'base' with stride S; tw1 = first twiddle.
template<int S, bool TW>
__device__ __forceinline__ void bfly8(float2* __restrict__ z, int base, float2 tw1) {
    float2 x0 = z[POFF(base + 0 * S)];
    float2 x1 = z[POFF(base + 1 * S)];
    float2 x2 = z[POFF(base + 2 * S)];
    float2 x3 = z[POFF(base + 3 * S)];
    float2 x4 = z[POFF(base + 4 * S)];
    float2 x5 = z[POFF(base + 5 * S)];
    float2 x6 = z[POFF(base + 6 * S)];
    float2 x7 = z[POFF(base + 7 * S)];

    float2 t0 = cadd(x0, x4), t4 = csub(x0, x4);
    float2 t1 = cadd(x1, x5), t5 = csub(x1, x5);
    float2 t2 = cadd(x2, x6), t6 = csub(x2, x6);
    float2 t3 = cadd(x3, x7), t7 = csub(x3, x7);

    float2 u0 = cadd(t0, t2), u2 = csub(t0, t2);
    float2 u1 = cadd(t1, t3), u3 = csub(t1, t3);
    float2 y0 = cadd(u0, u1);
    float2 y4 = csub(u0, u1);
    float2 y2 = make_float2(u2.x + u3.y, u2.y - u3.x);
    float2 y6 = make_float2(u2.x - u3.y, u2.y + u3.x);

    float2 w0 = t4;
    float2 w1 = make_float2(C8 * (t5.x + t5.y), C8 * (t5.y - t5.x));
    float2 w2 = make_float2(t6.y, -t6.x);
    float2 w3 = make_float2(C8 * (t7.y - t7.x), -C8 * (t7.x + t7.y));
    float2 p0 = cadd(w0, w2), p2 = csub(w0, w2);
    float2 p1 = cadd(w1, w3), p3 = csub(w1, w3);
    float2 y1 = cadd(p0, p1);
    float2 y5 = csub(p0, p1);
    float2 y3 = make_float2(p2.x + p3.y, p2.y - p3.x);
    float2 y7 = make_float2(p2.x - p3.y, p2.y + p3.x);

    if (TW) {
        float2 tw2 = cmul(tw1, tw1);
        float2 tw3 = cmul(tw2, tw1);
        float2 tw4 = cmul(tw2, tw2);
        float2 tw5 = cmul(tw3, tw2);
        float2 tw6 = cmul(tw3, tw3);
        float2 tw7 = cmul(tw4, tw3);
        y1 = cmul(y1, tw1);
        y2 = cmul(y2, tw2);
        y3 = cmul(y3, tw3);
        y4 = cmul(y4, tw4);
        y5 = cmul(y5, tw5);
        y6 = cmul(y6, tw6);
        y7 = cmul(y7, tw7);
    }

    z[POFF(base + 0 * S)] = y0;
    z[POFF(base + 1 * S)] = y1;
    z[POFF(base + 2 * S)] = y2;
    z[POFF(base + 3 * S)] = y3;
    z[POFF(base + 4 * S)] = y4;
    z[POFF(base + 5 * S)] = y5;
    z[POFF(base + 6 * S)] = y6;
    z[POFF(base + 7 * S)] = y7;
}

// octal digit reverse of 12-bit index
__device__ __forceinline__ int drev(int k) {
    return ((k & 7) << 9) | (((k >> 3) & 7) << 6) | (((k >> 6) & 7) << 3) | ((k >> 9) & 7);
}

// peak/valley classifier for element i with value Cv, neighbors Lv/Rv
#define CLASSIFY(Lv, Cv, Rv, i)                                        \
    do {                                                               \
        if ((Cv) > (Lv) && (Cv) > (Rv)) {                              \
            cnt += 1;                                                  \
            if (p0 == N) p0 = (i);                                     \
        } else if ((Cv) < (Lv) && (Cv) < (Rv)) {                       \
            cnt += (1 << 16);                                          \
            if (vs1 == N) vs1 = (i);                                   \
            else if (vs2 == N) vs2 = (i);                              \
            vlast = (i);                                               \
        }                                                              \
    } while (0)

// ---------------- main kernel: one CTA per row -------------------------------
__global__ __launch_bounds__(NT, 4)
void feat_kernel(const float* __restrict__ xin, float* __restrict__ out, int nrows) {
    extern __shared__ float smf[];           // SMEM_F2 float2 = 36864 B
    float2* z = (float2*)smf;
    __shared__ float csum[NT];               // per-thread contiguous-chunk sums
    __shared__ float cexc[NT];               // exclusive prefix over chunks
    __shared__ float wtot[NT / 32];
    __shared__ float woff[NT / 32];
    __shared__ float stot_sh;

    int row = blockIdx.x;
    if (row >= nrows) return;
    const float*  xr = xin + (size_t)row * N;
    const float4* x4 = (const float4*)xr;
    int tid  = threadIdx.x;
    int lane = tid & 31;
    int wrp  = tid >> 5;

    // ---- fused pass 1: load contiguous chunk [32*tid, 32*tid+31], compute
    //      stats, chunk sum, peak/valley classification, store smem pairs ----
    float mx = -3.4e38f, mn = 3.4e38f, s2 = 0.f, cs = 0.f;
    int cnt = 0;                 // npk + (nvl<<16)
    int p0 = N, vs1 = N, vs2 = N, vlast = -1;
    int base = 32 * tid;
    float xm1 = (tid > 0)      ? xr[base - 1]  : 0.f;
    float xp1 = (tid < NT - 1) ? xr[base + 32] : 0.f;
    float L = xm1, C = 0.f;
    #pragma unroll
    for (int rep = 0; rep < 8; rep++) {
        float4 f = x4[tid * 8 + rep];
        mx = fmaxf(fmaxf(mx, f.x), fmaxf(f.y, fmaxf(f.z, f.w)));
        mn = fminf(fminf(mn, f.x), fminf(f.y, fminf(f.z, f.w)));
        s2 += (f.x * f.x + f.y * f.y) + (f.z * f.z + f.w * f.w);
        cs += (f.x + f.y) + (f.z + f.w);
        int pr = 16 * tid + 2 * rep;
        z[POFF(pr)]     = make_float2(f.x, f.y);
        z[POFF(pr + 1)] = make_float2(f.z, f.w);
        if (rep == 0) {
            if (tid > 0) CLASSIFY(L, f.x, f.y, base);     // local j = 0
            CLASSIFY(f.x, f.y, f.z, base + 1);
            CLASSIFY(f.y, f.z, f.w, base + 2);
        } else {
            CLASSIFY(L, C, f.x, base + 4 * rep - 1);
            CLASSIFY(C, f.x, f.y, base + 4 * rep);
            CLASSIFY(f.x, f.y, f.z, base + 4 * rep + 1);
            CLASSIFY(f.y, f.z, f.w, base + 4 * rep + 2);
        }
        L = f.z; C = f.w;
    }
    if (tid < NT - 1) CLASSIFY(L, C, xp1, base + 31);     // local j = 31
    csum[tid] = cs;
    __syncthreads();

    // ---- reductions ------------------------------------------------------
    mx = bredMaxF(mx);
    mn = bredMinF(mn);
    s2 = bredSumF(s2);
    cnt   = bredSumI(cnt);
    p0    = bredMinI(p0);
    vlast = bredMaxI(vlast);
    bredMin2I(vs1, vs2);
    int npk = cnt & 0xffff, nvl = cnt >> 16;
    int v0 = vs1, v1 = vs2;

    // ---- block scan over 256 chunk sums (prefix for trapezoid queries) ---
    {
        float inc = cs;
        #pragma unroll
        for (int o = 1; o < 32; o <<= 1) {
            float f = __shfl_up_sync(0xffffffffu, inc, o);
            if (lane >= o) inc += f;
        }
        if (lane == 31) wtot[wrp] = inc;
        __syncthreads();
        if (tid == 0) {
            float acc = 0.f;
            #pragma unroll
            for (int w = 0; w < NT / 32; w++) { woff[w] = acc; acc += wtot[w]; }
            stot_sh = acc;
        }
        __syncthreads();
        cexc[tid] = woff[wrp] + inc - cs;    // exclusive prefix of chunk sums
        __syncthreads();
    }

    bool valid = (npk >= 1) && (nvl >= 2);
    float PA = 0.f, A2 = 0.f, A1 = 0.f, PH = 0.f, PWHH = 0.f;

    if (valid) {
        float sp0 = smf[XIDX(p0)];
        float sv0 = smf[XIDX(v0)];
        PH = sp0 - sv0;
        float hh = (sp0 + sv0) * 0.5f;

        // half-height indices: only over [v0, p0] (typically a few samples)
        int li = N, ri = -1;
        for (int i = v0 + tid; i <= p0; i += NT) {
            float c = smf[XIDX(i)];
            if (c >= hh) {
                if (i < p0) li = min(li, i);
                if (i > v0) ri = max(ri, i);
            }
        }
        li = bredMinI(li);
        ri = bredMaxI(ri);
        if (li == N)  li = v0;
        if (ri == -1) ri = p0;
        PWHH = (float)(ri - li) / SRf;

        // trapezoids via prefix point queries (warp 0 only)
        // T(a,b) = (P[b-2] - P[a] + 0.5*x[a] + 0.5*x[b-1]) / SR, 0 if b-2 < a
        if (wrp == 0) {
            auto Pq = [&](int idx) -> float {
                int c = idx >> 5;
                float v = (lane <= (idx & 31)) ? smf[XIDX((c << 5) + lane)] : 0.f;
                #pragma unroll
                for (int o = 16; o; o >>= 1) v += __shfl_down_sync(0xffffffffu, v, o);
                v = __shfl_sync(0xffffffffu, v, 0);
                return cexc[c] + v;
            };
            float Pv0 = Pq(v0);
            PA = (Pq(vlast - 2) - Pv0 + 0.5f * (sv0 + smf[XIDX(vlast - 1)])) * (1.0f / SRf);
            if (v1 - 2 >= p0)
                A2 = (Pq(v1 - 2) - Pq(p0) + 0.5f * (sp0 + smf[XIDX(v1 - 1)])) * (1.0f / SRf);
            if (p0 - 2 >= v0)
                A1 = (Pq(p0 - 2) - Pv0 + 0.5f * (sv0 + smf[XIDX(p0 - 1)])) * (1.0f / SRf);
        }
    }
    __syncthreads();   // all smem reads done before FFT overwrites

    // ---- FFT: z[n] = x[2n] + i x[2n+1], 4096-pt, 4 radix-8 DIF passes ----
    // pass 1: L=4096, S=512; rep1 twiddle = rep0 twiddle * exp(-i*pi/8)
    {
        float sn, csn;
        __sincosf(-2.0f * PI_F * (float)tid / 4096.0f, &sn, &csn);
        float2 tw = make_float2(csn, sn);
        bfly8<512, true>(z, tid, tw);
        const float2 wstep = make_float2(0.92387953251128674f, -0.38268343236508978f);
        float2 twb = cmul(tw, wstep);
        bfly8<512, true>(z, tid + 256, twb);
    }
    __syncthreads();
    // pass 2: L=512, S=64; both reps share t = tid & 63
    {
        int t = tid & 63;
        float sn, csn;
        __sincosf(-2.0f * PI_F * (float)t / 512.0f, &sn, &csn);
        float2 tw = make_float2(csn, sn);
        bfly8<64, true>(z, (tid >> 6) * 512 + t, tw);
        bfly8<64, true>(z, ((tid + 256) >> 6) * 512 + t, tw);
    }
    __syncthreads();
    // pass 3: L=64, S=8; both reps share t = tid & 7
    {
        int t = tid & 7;
        float sn, csn;
        __sincosf(-2.0f * PI_F * (float)t / 64.0f, &sn, &csn);
        float2 tw = make_float2(csn, sn);
        bfly8<8, true>(z, (tid >> 3) * 64 + t, tw);
        bfly8<8, true>(z, ((tid + 256) >> 3) * 64 + t, tw);
    }
    __syncthreads();
    // pass 4: L=8, S=1, twiddle-free
    {
        float2 dummy = make_float2(1.f, 0.f);
        bfly8<1, false>(z, tid * 8, dummy);
        bfly8<1, false>(z, (tid + 256) * 8, dummy);
    }
    __syncthreads();

    // ---- unpack real FFT + magnitude sum (halved via conjugate symmetry) --
    // total = (a0+b0) + 2*sum_{k=1..2047}(a_k+b_k) + 2*|X[2048]|,
    //   a_k = |X[k]| = |Ze + W^k Zo|, b_k = |X[k+M]| = |Ze - W^k Zo|.
    // Lane->k map k = lane*64 + wrp + 8*rep puts lane bits in k's HIGH octal
    // digits, so drev(k) varies in LOW digits across a warp -> ~2-way (floor).
    float fs = 0.f;
    {
        int k0 = lane * 64 + wrp;
        float2 Wk;
        {
            float sn, csn;
            __sincosf(-PI_F * (float)k0 / (float)M, &sn, &csn);
            Wk = make_float2(csn, sn);
        }
        // step = exp(-i*pi*8/4096) = exp(-i*pi/512)
        const float2 Wstep = make_float2(0.99998117528260111f, -0.0061358846491544753f);
        #pragma unroll
        for (int rep = 0; rep < 8; rep++) {
            int k  = k0 + 8 * rep;
            int km = (M - k) & (M - 1);
            float2 Zk = z[POFF(drev(k))];
            float2 Zm = z[POFF(drev(km))];
            float2 Ze = make_float2(0.5f * (Zk.x + Zm.x), 0.5f * (Zk.y - Zm.y));
            float2 Bv = make_float2(0.5f * (Zk.x - Zm.x), 0.5f * (Zk.y + Zm.y));
            float2 Zo = make_float2(Bv.y, -Bv.x);
            float2 WZo = cmul(Wk, Zo);
            float ax = Ze.x + WZo.x, ay = Ze.y + WZo.y;
            float bx = Ze.x - WZo.x, by = Ze.y - WZo.y;
            float mag = fsqrt_ap(ax * ax + ay * ay) + fsqrt_ap(bx * bx + by * by);
            fs += (k == 0) ? mag : 2.0f * mag;
            Wk = cmul(Wk, Wstep);
        }
        if (tid == 0) {
            // k = 2048 term: X[2048] at storage drev(2048) = 4
            float2 Zk = z[POFF(4)];
            fs += 2.0f * fsqrt_ap(Zk.x * Zk.x + Zk.y * Zk.y);
        }
    }
    fs = bredSumF(fs);
    float fftm = fs * (1.0f / (float)N);

    // ---- write output ----------------------------------------------------
    if (tid == 0) {
        float s    = stot_sh;
        float mean = s * (1.0f / (float)N);
        float var  = (s2 - s * mean) * (1.0f / (float)(N - 1));
        float sd   = sqrtf(var);
        float* o = out + (size_t)row * 10;
        o[0] = mx;
        o[1] = mx - mn;
        o[2] = var;
        o[3] = sd;
        o[4] = fftm;
        o[5] = valid ? PA : 0.f;
        o[6] = valid ? A2 : 0.f;
        o[7] = valid ? PH : 0.f;
        o[8] = valid ? A1 : 0.f;
        o[9] = valid ? PWHH : 0.f;
    }
}

extern "C" void kernel_launch(void* const* d_in, const int* in_sizes, int n_in,
                              void* d_out, int out_size) {
    const float* x = (const float*)d_in[0];
    float* out = (float*)d_out;
    int nrows = in_sizes[0] / N;  // 2048
    size_t smem_bytes = (size_t)SMEM_F2 * sizeof(float2);  // 36864 B
    cudaFuncSetAttribute(feat_kernel, cudaFuncAttributeMaxDynamicSharedMemorySize,
                         (int)smem_bytes);
    feat_kernel<<<nrows, NT, smem_bytes>>>(x, out, nrows);
}

// round 13
// speedup vs baseline: 6.1699x; 1.0811x over previous
#include <cuda_runtime.h>
#include <math.h>

#define N     8192          // real signal length
#define M     4096          // packed complex length
#define NT    256
#define SRf   30.0f
#define PI_F  3.14159265358979f
#define C8    0.70710678118654752f   // sqrt(2)/2

// padded complex offset: one extra float2 per 16 -> conflict-free for
// contiguous-lane passes (S=512/64), pass4 (8t+floor(t/2) pattern), and the
// load-phase stride-16 stores. Pass 3 (S=8) uses a remapped lane->butterfly
// assignment (see below) to stay conflict-free under this pad.
#define POFF(n)  ((n) + ((n) >> 4))
// scalar view of x[i] inside the padded complex buffer (z[n].x=x[2n], .y=x[2n+1])
#define XIDX(i)  (((((i) >> 1) + ((i) >> 5)) << 1) | ((i) & 1))

#define SMEM_F2  (M + M / 16)        // 4352 float2 = 34816 B

__device__ __forceinline__ float fsqrt_ap(float x) {
    float r; asm("sqrt.approx.f32 %0, %1;" : "=f"(r) : "f"(x)); return r;
}

// ---------------- block reductions (deterministic) ---------------------------
__device__ __forceinline__ float bredSumF(float v) {
    __shared__ float scr[8];
    int lane = threadIdx.x & 31, w = threadIdx.x >> 5;
    #pragma unroll
    for (int o = 16; o; o >>= 1) v += __shfl_down_sync(0xffffffffu, v, o);
    __syncthreads();
    if (lane == 0) scr[w] = v;
    __syncthreads();
    if (threadIdx.x == 0) {
        float r = scr[0];
        #pragma unroll
        for (int i = 1; i < NT / 32; i++) r += scr[i];
        scr[0] = r;
    }
    __syncthreads();
    v = scr[0];
    __syncthreads();
    return v;
}
__device__ __forceinline__ float bredMaxF(float v) {
    __shared__ float scr[8];
    int lane = threadIdx.x & 31, w = threadIdx.x >> 5;
    #pragma unroll
    for (int o = 16; o; o >>= 1) v = fmaxf(v, __shfl_down_sync(0xffffffffu, v, o));
    __syncthreads();
    if (lane == 0) scr[w] = v;
    __syncthreads();
    if (threadIdx.x == 0) {
        float r = scr[0];
        #pragma unroll
        for (int i = 1; i < NT / 32; i++) r = fmaxf(r, scr[i]);
        scr[0] = r;
    }
    __syncthreads();
    v = scr[0];
    __syncthreads();
    return v;
}
__device__ __forceinline__ float bredMinF(float v) {
    __shared__ float scr[8];
    int lane = threadIdx.x & 31, w = threadIdx.x >> 5;
    #pragma unroll
    for (int o = 16; o; o >>= 1) v = fminf(v, __shfl_down_sync(0xffffffffu, v, o));
    __syncthreads();
    if (lane == 0) scr[w] = v;
    __syncthreads();
    if (threadIdx.x == 0) {
        float r = scr[0];
        #pragma unroll
        for (int i = 1; i < NT / 32; i++) r = fminf(r, scr[i]);
        scr[0] = r;
    }
    __syncthreads();
    v = scr[0];
    __syncthreads();
    return v;
}
__device__ __forceinline__ int bredSumI(int v) {
    __shared__ int scr[8];
    int lane = threadIdx.x & 31, w = threadIdx.x >> 5;
    #pragma unroll
    for (int o = 16; o; o >>= 1) v += __shfl_down_sync(0xffffffffu, v, o);
    __syncthreads();
    if (lane == 0) scr[w] = v;
    __syncthreads();
    if (threadIdx.x == 0) {
        int r = scr[0];
        #pragma unroll
        for (int i = 1; i < NT / 32; i++) r += scr[i];
        scr[0] = r;
    }
    __syncthreads();
    v = scr[0];
    __syncthreads();
    return v;
}
__device__ __forceinline__ int bredMinI(int v) {
    __shared__ int scr[8];
    int lane = threadIdx.x & 31, w = threadIdx.x >> 5;
    #pragma unroll
    for (int o = 16; o; o >>= 1) v = min(v, __shfl_down_sync(0xffffffffu, v, o));
    __syncthreads();
    if (lane == 0) scr[w] = v;
    __syncthreads();
    if (threadIdx.x == 0) {
        int r = scr[0];
        #pragma unroll
        for (int i = 1; i < NT / 32; i++) r = min(r, scr[i]);
        scr[0] = r;
    }
    __syncthreads();
    v = scr[0];
    __syncthreads();
    return v;
}
__device__ __forceinline__ int bredMaxI(int v) {
    __shared__ int scr[8];
    int lane = threadIdx.x & 31, w = threadIdx.x >> 5;
    #pragma unroll
    for (int o = 16; o; o >>= 1) v = max(v, __shfl_down_sync(0xffffffffu, v, o));
    __syncthreads();
    if (lane == 0) scr[w] = v;
    __syncthreads();
    if (threadIdx.x == 0) {
        int r = scr[0];
        #pragma unroll
        for (int i = 1; i < NT / 32; i++) r = max(r, scr[i]);
        scr[0] = r;
    }
    __syncthreads();
    v = scr[0];
    __syncthreads();
    return v;
}
// two smallest values across block (s1 <= s2 per thread on entry)
__device__ __forceinline__ void bredMin2I(int& s1, int& s2) {
    __shared__ int scr2[16];
    int lane = threadIdx.x & 31, w = threadIdx.x >> 5;
    #pragma unroll
    for (int o = 16; o; o >>= 1) {
        int o1 = __shfl_down_sync(0xffffffffu, s1, o);
        int o2 = __shfl_down_sync(0xffffffffu, s2, o);
        int n1 = min(s1, o1);
        int n2 = min(max(s1, o1), min(s2, o2));
        s1 = n1; s2 = n2;
    }
    __syncthreads();
    if (lane == 0) { scr2[w * 2] = s1; scr2[w * 2 + 1] = s2; }
    __syncthreads();
    if (threadIdx.x == 0) {
        int a1 = scr2[0], a2 = scr2[1];
        #pragma unroll
        for (int i = 1; i < NT / 32; i++) {
            int b1 = scr2[i * 2], b2 = scr2[i * 2 + 1];
            int n1 = min(a1, b1);
            int n2 = min(max(a1, b1), min(a2, b2));
            a1 = n1; a2 = n2;
        }
        scr2[0] = a1; scr2[1] = a2;
    }
    __syncthreads();
    s1 = scr2[0]; s2 = scr2[1];
    __syncthreads();
}

// ---------------- complex helpers -------------------------------------------
__device__ __forceinline__ float2 cadd(float2 a, float2 b) { return make_float2(a.x + b.x, a.y + b.y); }
__device__ __forceinline__ float2 csub(float2 a, float2 b) { return make_float2(a.x - b.x, a.y - b.y); }
__device__ __forceinline__ float2 cmul(float2 a, float2 b) {
    return make_float2(a.x * b.x - a.y * b.y, a.x * b.y + a.y * b.x);
}

// one radix-8 DIF butterfly at 'base' with stride S; tw1 = first twiddle.
template<int S, bool TW>
__device__ __forceinline__ void bfly8(float2* __restrict__ z, int base, float2 tw1) {
    float2 x0 = z[POFF(base + 0 * S)];
    float2 x1 = z[POFF(base + 1 * S)];
    float2 x2 = z[POFF(base + 2 * S)];
    float2 x3 = z[POFF(base + 3 * S)];
    float2 x4 = z[POFF(base + 4 * S)];
    float2 x5 = z[POFF(base + 5 * S)];
    float2 x6 = z[POFF(base + 6 * S)];
    float2 x7 = z[POFF(base + 7 * S)];

    float2 t0 = cadd(x0, x4), t4 = csub(x0, x4);
    float2 t1 = cadd(x1, x5), t5 = csub(x1, x5);
    float2 t2 = cadd(x2, x6), t6 = csub(x2, x6);
    float2 t3 = cadd(x3, x7), t7 = csub(x3, x7);

    float2 u0 = cadd(t0, t2), u2 = csub(t0, t2);
    float2 u1 = cadd(t1, t3), u3 = csub(t1, t3);
    float2 y0 = cadd(u0, u1);
    float2 y4 = csub(u0, u1);
    float2 y2 = make_float2(u2.x + u3.y, u2.y - u3.x);
    float2 y6 = make_float2(u2.x - u3.y, u2.y + u3.x);

    float2 w0 = t4;
    float2 w1 = make_float2(C8 * (t5.x + t5.y), C8 * (t5.y - t5.x));
    float2 w2 = make_float2(t6.y, -t6.x);
    float2 w3 = make_float2(C8 * (t7.y - t7.x), -C8 * (t7.x + t7.y));
    float2 p0 = cadd(w0, w2), p2 = csub(w0, w2);
    float2 p1 = cadd(w1, w3), p3 = csub(w1, w3);
    float2 y1 = cadd(p0, p1);
    float2 y5 = csub(p0, p1);
    float2 y3 = make_float2(p2.x + p3.y, p2.y - p3.x);
    float2 y7 = make_float2(p2.x - p3.y, p2.y + p3.x);

    if (TW) {
        float2 tw2 = cmul(tw1, tw1);
        float2 tw3 = cmul(tw2, tw1);
        float2 tw4 = cmul(tw2, tw2);
        float2 tw5 = cmul(tw3, tw2);
        float2 tw6 = cmul(tw3, tw3);
        float2 tw7 = cmul(tw4, tw3);
        y1 = cmul(y1, tw1);
        y2 = cmul(y2, tw2);
        y3 = cmul(y3, tw3);
        y4 = cmul(y4, tw4);
        y5 = cmul(y5, tw5);
        y6 = cmul(y6, tw6);
        y7 = cmul(y7, tw7);
    }

    z[POFF(base + 0 * S)] = y0;
    z[POFF(base + 1 * S)] = y1;
    z[POFF(base + 2 * S)] = y2;
    z[POFF(base + 3 * S)] = y3;
    z[POFF(base + 4 * S)] = y4;
    z[POFF(base + 5 * S)] = y5;
    z[POFF(base + 6 * S)] = y6;
    z[POFF(base + 7 * S)] = y7;
}

// octal digit reverse of 12-bit index
__device__ __forceinline__ int drev(int k) {
    return ((k & 7) << 9) | (((k >> 3) & 7) << 6) | (((k >> 6) & 7) << 3) | ((k >> 9) & 7);
}

// peak/valley classifier for element i with value Cv, neighbors Lv/Rv
#define CLASSIFY(Lv, Cv, Rv, i)                                        \
    do {                                                               \
        if ((Cv) > (Lv) && (Cv) > (Rv)) {                              \
            cnt += 1;                                                  \
            if (p0 == N) p0 = (i);                                     \
        } else if ((Cv) < (Lv) && (Cv) < (Rv)) {                       \
            cnt += (1 << 16);                                          \
            if (vs1 == N) vs1 = (i);                                   \
            else if (vs2 == N) vs2 = (i);                              \
            vlast = (i);                                               \
        }                                                              \
    } while (0)

// ---------------- main kernel: one CTA per row -------------------------------
__global__ __launch_bounds__(NT, 4)
void feat_kernel(const float* __restrict__ xin, float* __restrict__ out, int nrows) {
    extern __shared__ float smf[];           // SMEM_F2 float2 = 34816 B
    float2* z = (float2*)smf;
    __shared__ float csum[NT];               // per-thread contiguous-chunk sums
    __shared__ float cexc[NT];               // exclusive prefix over chunks
    __shared__ float wtot[NT / 32];
    __shared__ float woff[NT / 32];
    __shared__ float stot_sh;

    int row = blockIdx.x;
    if (row >= nrows) return;
    const float*  xr = xin + (size_t)row * N;
    const float4* x4 = (const float4*)xr;
    int tid  = threadIdx.x;
    int lane = tid & 31;
    int wrp  = tid >> 5;

    // ---- fused pass 1: load contiguous chunk [32*tid, 32*tid+31], compute
    //      stats, chunk sum, peak/valley classification, store smem pairs ----
    float mx = -3.4e38f, mn = 3.4e38f, s2 = 0.f, cs = 0.f;
    int cnt = 0;                 // npk + (nvl<<16)
    int p0 = N, vs1 = N, vs2 = N, vlast = -1;
    int base = 32 * tid;
    float xm1 = (tid > 0)      ? xr[base - 1]  : 0.f;
    float xp1 = (tid < NT - 1) ? xr[base + 32] : 0.f;
    float L = xm1, C = 0.f;
    #pragma unroll
    for (int rep = 0; rep < 8; rep++) {
        float4 f = x4[tid * 8 + rep];
        mx = fmaxf(fmaxf(mx, f.x), fmaxf(f.y, fmaxf(f.z, f.w)));
        mn = fminf(fminf(mn, f.x), fminf(f.y, fminf(f.z, f.w)));
        s2 += (f.x * f.x + f.y * f.y) + (f.z * f.z + f.w * f.w);
        cs += (f.x + f.y) + (f.z + f.w);
        int pr = 16 * tid + 2 * rep;
        z[POFF(pr)]     = make_float2(f.x, f.y);
        z[POFF(pr + 1)] = make_float2(f.z, f.w);
        if (rep == 0) {
            if (tid > 0) CLASSIFY(L, f.x, f.y, base);     // local j = 0
            CLASSIFY(f.x, f.y, f.z, base + 1);
            CLASSIFY(f.y, f.z, f.w, base + 2);
        } else {
            CLASSIFY(L, C, f.x, base + 4 * rep - 1);
            CLASSIFY(C, f.x, f.y, base + 4 * rep);
            CLASSIFY(f.x, f.y, f.z, base + 4 * rep + 1);
            CLASSIFY(f.y, f.z, f.w, base + 4 * rep + 2);
        }
        L = f.z; C = f.w;
    }
    if (tid < NT - 1) CLASSIFY(L, C, xp1, base + 31);     // local j = 31
    csum[tid] = cs;
    __syncthreads();

    // ---- reductions ------------------------------------------------------
    mx = bredMaxF(mx);
    mn = bredMinF(mn);
    s2 = bredSumF(s2);
    cnt   = bredSumI(cnt);
    p0    = bredMinI(p0);
    vlast = bredMaxI(vlast);
    bredMin2I(vs1, vs2);
    int npk = cnt & 0xffff, nvl = cnt >> 16;
    int v0 = vs1, v1 = vs2;

    // ---- block scan over 256 chunk sums (prefix for trapezoid queries) ---
    {
        float inc = cs;
        #pragma unroll
        for (int o = 1; o < 32; o <<= 1) {
            float f = __shfl_up_sync(0xffffffffu, inc, o);
            if (lane >= o) inc += f;
        }
        if (lane == 31) wtot[wrp] = inc;
        __syncthreads();
        if (tid == 0) {
            float acc = 0.f;
            #pragma unroll
            for (int w = 0; w < NT / 32; w++) { woff[w] = acc; acc += wtot[w]; }
            stot_sh = acc;
        }
        __syncthreads();
        cexc[tid] = woff[wrp] + inc - cs;    // exclusive prefix of chunk sums
        __syncthreads();
    }

    bool valid = (npk >= 1) && (nvl >= 2);
    float PA = 0.f, A2 = 0.f, A1 = 0.f, PH = 0.f, PWHH = 0.f;

    if (valid) {
        float sp0 = smf[XIDX(p0)];
        float sv0 = smf[XIDX(v0)];
        PH = sp0 - sv0;
        float hh = (sp0 + sv0) * 0.5f;

        // half-height indices: only over [v0, p0] (typically a few samples)
        int li = N, ri = -1;
        for (int i = v0 + tid; i <= p0; i += NT) {
            float c = smf[XIDX(i)];
            if (c >= hh) {
                if (i < p0) li = min(li, i);
                if (i > v0) ri = max(ri, i);
            }
        }
        li = bredMinI(li);
        ri = bredMaxI(ri);
        if (li == N)  li = v0;
        if (ri == -1) ri = p0;
        PWHH = (float)(ri - li) / SRf;

        // trapezoids via prefix point queries (warp 0 only)
        // T(a,b) = (P[b-2] - P[a] + 0.5*x[a] + 0.5*x[b-1]) / SR, 0 if b-2 < a
        if (wrp == 0) {
            auto Pq = [&](int idx) -> float {
                int c = idx >> 5;
                float v = (lane <= (idx & 31)) ? smf[XIDX((c << 5) + lane)] : 0.f;
                #pragma unroll
                for (int o = 16; o; o >>= 1) v += __shfl_down_sync(0xffffffffu, v, o);
                v = __shfl_sync(0xffffffffu, v, 0);
                return cexc[c] + v;
            };
            float Pv0 = Pq(v0);
            PA = (Pq(vlast - 2) - Pv0 + 0.5f * (sv0 + smf[XIDX(vlast - 1)])) * (1.0f / SRf);
            if (v1 - 2 >= p0)
                A2 = (Pq(v1 - 2) - Pq(p0) + 0.5f * (sp0 + smf[XIDX(v1 - 1)])) * (1.0f / SRf);
            if (p0 - 2 >= v0)
                A1 = (Pq(p0 - 2) - Pv0 + 0.5f * (sv0 + smf[XIDX(p0 - 1)])) * (1.0f / SRf);
        }
    }
    __syncthreads();   // all smem reads done before FFT overwrites

    // ---- FFT: z[n] = x[2n] + i x[2n+1], 4096-pt, 4 radix-8 DIF passes ----
    // pass 1: L=4096, S=512; rep1 twiddle = rep0 twiddle * exp(-i*pi/8)
    {
        float sn, csn;
        __sincosf(-2.0f * PI_F * (float)tid / 4096.0f, &sn, &csn);
        float2 tw = make_float2(csn, sn);
        bfly8<512, true>(z, tid, tw);
        const float2 wstep = make_float2(0.92387953251128674f, -0.38268343236508978f);
        float2 twb = cmul(tw, wstep);
        bfly8<512, true>(z, tid + 256, twb);
    }
    __syncthreads();
    // pass 2: L=512, S=64; both reps share t = tid & 63
    {
        int t = tid & 63;
        float sn, csn;
        __sincosf(-2.0f * PI_F * (float)t / 512.0f, &sn, &csn);
        float2 tw = make_float2(csn, sn);
        bfly8<64, true>(z, (tid >> 6) * 512 + t, tw);
        bfly8<64, true>(z, ((tid + 256) >> 6) * 512 + t, tw);
    }
    __syncthreads();
    // pass 3: L=64, S=8; remapped lane->butterfly assignment for the pad-16
    // layout: idx = rep*256 + tid, t = (idx>>2)&7, blk = (idx&3) + 4*(idx>>5).
    // Per phase, banks = 4*(lane&3) + (lane>>2) -> all 16 distinct. Both reps
    // share t (adding 256 to idx leaves (idx>>2)&7 unchanged), so one sincos.
    {
        int t = (tid >> 2) & 7;
        float sn, csn;
        __sincosf(-2.0f * PI_F * (float)t / 64.0f, &sn, &csn);
        float2 tw = make_float2(csn, sn);
        int blk0 = (tid & 3) + 4 * (tid >> 5);
        bfly8<8, true>(z, blk0 * 64 + t, tw);
        int blk1 = (tid & 3) + 4 * ((tid + 256) >> 5);
        bfly8<8, true>(z, blk1 * 64 + t, tw);
    }
    __syncthreads();
    // pass 4: L=8, S=1, twiddle-free
    {
        float2 dummy = make_float2(1.f, 0.f);
        bfly8<1, false>(z, tid * 8, dummy);
        bfly8<1, false>(z, (tid + 256) * 8, dummy);
    }
    __syncthreads();

    // ---- unpack real FFT + magnitude sum (halved via conjugate symmetry) --
    // total = (a0+b0) + 2*sum_{k=1..2047}(a_k+b_k) + 2*|X[2048]|,
    //   a_k = |X[k]| = |Ze + W^k Zo|, b_k = |X[k+M]| = |Ze - W^k Zo|.
    // Lane->k map k = lane*64 + wrp + 8*rep puts lane bits in k's HIGH octal
    // digits, so drev(k) varies in LOW digits across a warp -> ~2-way (floor).
    float fs = 0.f;
    {
        int k0 = lane * 64 + wrp;
        float2 Wk;
        {
            float sn, csn;
            __sincosf(-PI_F * (float)k0 / (float)M, &sn, &csn);
            Wk = make_float2(csn, sn);
        }
        // step = exp(-i*pi*8/4096) = exp(-i*pi/512)
        const float2 Wstep = make_float2(0.99998117528260111f, -0.0061358846491544753f);
        #pragma unroll
        for (int rep = 0; rep < 8; rep++) {
            int k  = k0 + 8 * rep;
            int km = (M - k) & (M - 1);
            float2 Zk = z[POFF(drev(k))];
            float2 Zm = z[POFF(drev(km))];
            float2 Ze = make_float2(0.5f * (Zk.x + Zm.x), 0.5f * (Zk.y - Zm.y));
            float2 Bv = make_float2(0.5f * (Zk.x - Zm.x), 0.5f * (Zk.y + Zm.y));
            float2 Zo = make_float2(Bv.y, -Bv.x);
            float2 WZo = cmul(Wk, Zo);
            float ax = Ze.x + WZo.x, ay = Ze.y + WZo.y;
            float bx = Ze.x - WZo.x, by = Ze.y - WZo.y;
            float mag = fsqrt_ap(ax * ax + ay * ay) + fsqrt_ap(bx * bx + by * by);
            fs += (k == 0) ? mag : 2.0f * mag;
            Wk = cmul(Wk, Wstep);
        }
        if (tid == 0) {
            // k = 2048 term: X[2048] at storage drev(2048) = 4
            float2 Zk = z[POFF(4)];
            fs += 2.0f * fsqrt_ap(Zk.x * Zk.x + Zk.y * Zk.y);
        }
    }
    fs = bredSumF(fs);
    float fftm = fs * (1.0f / (float)N);

    // ---- write output ----------------------------------------------------
    if (tid == 0) {
        float s    = stot_sh;
        float mean = s * (1.0f / (float)N);
        float var  = (s2 - s * mean) * (1.0f / (float)(N - 1));
        float sd   = sqrtf(var);
        float* o = out + (size_t)row * 10;
        o[0] = mx;
        o[1] = mx - mn;
        o[2] = var;
        o[3] = sd;
        o[4] = fftm;
        o[5] = valid ? PA : 0.f;
        o[6] = valid ? A2 : 0.f;
        o[7] = valid ? PH : 0.f;
        o[8] = valid ? A1 : 0.f;
        o[9] = valid ? PWHH : 0.f;
    }
}

extern "C" void kernel_launch(void* const* d_in, const int* in_sizes, int n_in,
                              void* d_out, int out_size) {
    const float* x = (const float*)d_in[0];
    float* out = (float*)d_out;
    int nrows = in_sizes[0] / N;  // 2048
    size_t smem_bytes = (size_t)SMEM_F2 * sizeof(float2);  // 34816 B
    cudaFuncSetAttribute(feat_kernel, cudaFuncAttributeMaxDynamicSharedMemorySize,
                         (int)smem_bytes);
    feat_kernel<<<nrows, NT, smem_bytes>>>(x, out, nrows);
}

// round 14
// speedup vs baseline: 6.1729x; 1.0005x over previous
#include <cuda_runtime.h>
#include <math.h>

#define N     8192          // real signal length
#define M     4096          // packed complex length
#define NT    256
#define SRf   30.0f
#define PI_F  3.14159265358979f
#define C8    0.70710678118654752f   // sqrt(2)/2

// padded complex offset: one extra float2 per 16 -> conflict-free (see R13)
#define POFF(n)  ((n) + ((n) >> 4))
// scalar view of x[i] inside the padded complex buffer
#define XIDX(i)  (((((i) >> 1) + ((i) >> 5)) << 1) | ((i) & 1))

#define SMEM_F2  (M + M / 16)        // 4352 float2 = 34816 B

__device__ __forceinline__ float fsqrt_ap(float x) {
    float r; asm("sqrt.approx.f32 %0, %1;" : "=f"(r) : "f"(x)); return r;
}

// monotonic float<->uint key (total order for non-NaN floats)
__device__ __forceinline__ unsigned fkey(float f) {
    unsigned u = __float_as_uint(f);
    return (u >> 31) ? ~u : (u | 0x80000000u);
}
__device__ __forceinline__ float unkey(unsigned k) {
    unsigned u = (k >> 31) ? (k & 0x7fffffffu) : ~k;
    return __uint_as_float(u);
}

// ---------------- complex helpers -------------------------------------------
__device__ __forceinline__ float2 cadd(float2 a, float2 b) { return make_float2(a.x + b.x, a.y + b.y); }
__device__ __forceinline__ float2 csub(float2 a, float2 b) { return make_float2(a.x - b.x, a.y - b.y); }
__device__ __forceinline__ float2 cmul(float2 a, float2 b) {
    return make_float2(a.x * b.x - a.y * b.y, a.x * b.y + a.y * b.x);
}

// one radix-8 DIF butterfly at 'base' with stride S; tw1 = first twiddle.
template<int S, bool TW>
__device__ __forceinline__ void bfly8(float2* __restrict__ z, int base, float2 tw1) {
    float2 x0 = z[POFF(base + 0 * S)];
    float2 x1 = z[POFF(base + 1 * S)];
    float2 x2 = z[POFF(base + 2 * S)];
    float2 x3 = z[POFF(base + 3 * S)];
    float2 x4 = z[POFF(base + 4 * S)];
    float2 x5 = z[POFF(base + 5 * S)];
    float2 x6 = z[POFF(base + 6 * S)];
    float2 x7 = z[POFF(base + 7 * S)];

    float2 t0 = cadd(x0, x4), t4 = csub(x0, x4);
    float2 t1 = cadd(x1, x5), t5 = csub(x1, x5);
    float2 t2 = cadd(x2, x6), t6 = csub(x2, x6);
    float2 t3 = cadd(x3, x7), t7 = csub(x3, x7);

    float2 u0 = cadd(t0, t2), u2 = csub(t0, t2);
    float2 u1 = cadd(t1, t3), u3 = csub(t1, t3);
    float2 y0 = cadd(u0, u1);
    float2 y4 = csub(u0, u1);
    float2 y2 = make_float2(u2.x + u3.y, u2.y - u3.x);
    float2 y6 = make_float2(u2.x - u3.y, u2.y + u3.x);

    float2 w0 = t4;
    float2 w1 = make_float2(C8 * (t5.x + t5.y), C8 * (t5.y - t5.x));
    float2 w2 = make_float2(t6.y, -t6.x);
    float2 w3 = make_float2(C8 * (t7.y - t7.x), -C8 * (t7.x + t7.y));
    float2 p0 = cadd(w0, w2), p2 = csub(w0, w2);
    float2 p1 = cadd(w1, w3), p3 = csub(w1, w3);
    float2 y1 = cadd(p0, p1);
    float2 y5 = csub(p0, p1);
    float2 y3 = make_float2(p2.x + p3.y, p2.y - p3.x);
    float2 y7 = make_float2(p2.x - p3.y, p2.y + p3.x);

    if (TW) {
        float2 tw2 = cmul(tw1, tw1);
        float2 tw3 = cmul(tw2, tw1);
        float2 tw4 = cmul(tw2, tw2);
        float2 tw5 = cmul(tw3, tw2);
        float2 tw6 = cmul(tw3, tw3);
        float2 tw7 = cmul(tw4, tw3);
        y1 = cmul(y1, tw1);
        y2 = cmul(y2, tw2);
        y3 = cmul(y3, tw3);
        y4 = cmul(y4, tw4);
        y5 = cmul(y5, tw5);
        y6 = cmul(y6, tw6);
        y7 = cmul(y7, tw7);
    }

    z[POFF(base + 0 * S)] = y0;
    z[POFF(base + 1 * S)] = y1;
    z[POFF(base + 2 * S)] = y2;
    z[POFF(base + 3 * S)] = y3;
    z[POFF(base + 4 * S)] = y4;
    z[POFF(base + 5 * S)] = y5;
    z[POFF(base + 6 * S)] = y6;
    z[POFF(base + 7 * S)] = y7;
}

// octal digit reverse of 12-bit index
__device__ __forceinline__ int drev(int k) {
    return ((k & 7) << 9) | (((k >> 3) & 7) << 6) | (((k >> 6) & 7) << 3) | ((k >> 9) & 7);
}

// peak/valley classifier for element i with value Cv, neighbors Lv/Rv
#define CLASSIFY(Lv, Cv, Rv, i)                                        \
    do {                                                               \
        if ((Cv) > (Lv) && (Cv) > (Rv)) {                              \
            cnt += 1;                                                  \
            if (p0 == N) p0 = (i);                                     \
        } else if ((Cv) < (Lv) && (Cv) < (Rv)) {                       \
            cnt += (1 << 16);                                          \
            if (vs1 == N) vs1 = (i);                                   \
            else if (vs2 == N) vs2 = (i);                              \
            vlast = (i);                                               \
        }                                                              \
    } while (0)

// ---------------- main kernel: one CTA per row -------------------------------
__global__ __launch_bounds__(NT, 4)
void feat_kernel(const float* __restrict__ xin, float* __restrict__ out, int nrows) {
    extern __shared__ float smf[];           // SMEM_F2 float2 = 34816 B
    float2* z = (float2*)smf;
    // fused-reduction scratch
    __shared__ unsigned sKmx[8], sKmn[8];
    __shared__ float    sS2[8], sWt[8], sWoff[8];
    __shared__ int      sCnt[8], sP0[8], sVl[8], sV1[8], sV2[8];
    __shared__ float    finF[4];             // mx, mn, s2, stot
    __shared__ int      finI[5];             // cnt, p0, vlast, vs1, vs2
    __shared__ float    cexc[NT];            // exclusive prefix over chunks

    int row = blockIdx.x;
    if (row >= nrows) return;
    const float*  xr = xin + (size_t)row * N;
    const float4* x4 = (const float4*)xr;
    int tid  = threadIdx.x;
    int lane = tid & 31;
    int wrp  = tid >> 5;

    // ---- fused pass 1: load contiguous chunk [32*tid, 32*tid+31] ----------
    float mx = -3.4e38f, mn = 3.4e38f, s2 = 0.f, cs = 0.f;
    int cnt = 0;                 // npk + (nvl<<16)
    int p0 = N, vs1 = N, vs2 = N, vlast = -1;
    int base = 32 * tid;
    float xm1 = (tid > 0)      ? xr[base - 1]  : 0.f;
    float xp1 = (tid < NT - 1) ? xr[base + 32] : 0.f;
    float L = xm1, C = 0.f;
    #pragma unroll
    for (int rep = 0; rep < 8; rep++) {
        float4 f = x4[tid * 8 + rep];
        mx = fmaxf(fmaxf(mx, f.x), fmaxf(f.y, fmaxf(f.z, f.w)));
        mn = fminf(fminf(mn, f.x), fminf(f.y, fminf(f.z, f.w)));
        s2 += (f.x * f.x + f.y * f.y) + (f.z * f.z + f.w * f.w);
        cs += (f.x + f.y) + (f.z + f.w);
        int pr = 16 * tid + 2 * rep;
        z[POFF(pr)]     = make_float2(f.x, f.y);
        z[POFF(pr + 1)] = make_float2(f.z, f.w);
        if (rep == 0) {
            if (tid > 0) CLASSIFY(L, f.x, f.y, base);
            CLASSIFY(f.x, f.y, f.z, base + 1);
            CLASSIFY(f.y, f.z, f.w, base + 2);
        } else {
            CLASSIFY(L, C, f.x, base + 4 * rep - 1);
            CLASSIFY(C, f.x, f.y, base + 4 * rep);
            CLASSIFY(f.x, f.y, f.z, base + 4 * rep + 1);
            CLASSIFY(f.y, f.z, f.w, base + 4 * rep + 2);
        }
        L = f.z; C = f.w;
    }
    if (tid < NT - 1) CLASSIFY(L, C, xp1, base + 31);

    // ---- fused reduction, phase A: per-warp, zero barriers -----------------
    unsigned kmx = __reduce_max_sync(0xffffffffu, fkey(mx));
    unsigned kmn = __reduce_min_sync(0xffffffffu, fkey(mn));
    float s2w = s2;
    #pragma unroll
    for (int o = 16; o; o >>= 1) s2w += __shfl_down_sync(0xffffffffu, s2w, o);
    unsigned rcnt = __reduce_add_sync(0xffffffffu, (unsigned)cnt);
    int rp0 = __reduce_min_sync(0xffffffffu, p0);
    int rvl = __reduce_max_sync(0xffffffffu, vlast);
    int a1 = vs1, a2 = vs2;
    #pragma unroll
    for (int o = 16; o; o >>= 1) {
        int o1 = __shfl_down_sync(0xffffffffu, a1, o);
        int o2 = __shfl_down_sync(0xffffffffu, a2, o);
        int n1 = min(a1, o1);
        int n2 = min(max(a1, o1), min(a2, o2));
        a1 = n1; a2 = n2;
    }
    // inclusive scan of per-thread chunk sums within warp
    float inc = cs;
    #pragma unroll
    for (int o = 1; o < 32; o <<= 1) {
        float f = __shfl_up_sync(0xffffffffu, inc, o);
        if (lane >= o) inc += f;
    }
    if (lane == 0) {
        sKmx[wrp] = kmx; sKmn[wrp] = kmn; sS2[wrp] = s2w;
        sCnt[wrp] = (int)rcnt; sP0[wrp] = rp0; sVl[wrp] = rvl;
        sV1[wrp] = a1; sV2[wrp] = a2;
    }
    if (lane == 31) sWt[wrp] = inc;
    __syncthreads();                                     // barrier 1

    // ---- phase B: warp 0 combines across 8 warps ---------------------------
    if (wrp == 0) {
        unsigned bkmx = (lane < 8) ? sKmx[lane] : 0u;
        unsigned bkmn = (lane < 8) ? sKmn[lane] : 0xffffffffu;
        float    bs2  = (lane < 8) ? sS2[lane]  : 0.f;
        unsigned bcnt = (lane < 8) ? (unsigned)sCnt[lane] : 0u;
        int      bp0  = (lane < 8) ? sP0[lane]  : N;
        int      bvl  = (lane < 8) ? sVl[lane]  : -1;
        int      b1   = (lane < 8) ? sV1[lane]  : N;
        int      b2   = (lane < 8) ? sV2[lane]  : N;
        float    bwt  = (lane < 8) ? sWt[lane]  : 0.f;
        bkmx = __reduce_max_sync(0xffffffffu, bkmx);
        bkmn = __reduce_min_sync(0xffffffffu, bkmn);
        #pragma unroll
        for (int o = 16; o; o >>= 1) bs2 += __shfl_down_sync(0xffffffffu, bs2, o);
        bcnt = __reduce_add_sync(0xffffffffu, bcnt);
        bp0  = __reduce_min_sync(0xffffffffu, bp0);
        bvl  = __reduce_max_sync(0xffffffffu, bvl);
        #pragma unroll
        for (int o = 16; o; o >>= 1) {
            int o1 = __shfl_down_sync(0xffffffffu, b1, o);
            int o2 = __shfl_down_sync(0xffffffffu, b2, o);
            int n1 = min(b1, o1);
            int n2 = min(max(b1, o1), min(b2, o2));
            b1 = n1; b2 = n2;
        }
        // inclusive scan of warp totals (lanes >= 8 carry zeros)
        float winc = bwt;
        #pragma unroll
        for (int o = 1; o < 32; o <<= 1) {
            float f = __shfl_up_sync(0xffffffffu, winc, o);
            if (lane >= o) winc += f;
        }
        if (lane < 8) sWoff[lane] = winc - bwt;
        if (lane == 7) finF[3] = winc;                   // stot
        if (lane == 0) {
            finF[0] = unkey(bkmx); finF[1] = unkey(bkmn); finF[2] = bs2;
            finI[0] = (int)bcnt; finI[1] = bp0; finI[2] = bvl;
            finI[3] = b1; finI[4] = b2;
        }
    }
    __syncthreads();                                     // barrier 2

    mx = finF[0]; mn = finF[1]; s2 = finF[2];
    float stot = finF[3];
    cnt   = finI[0];
    p0    = finI[1];
    vlast = finI[2];
    int v0 = finI[3], v1 = finI[4];
    int npk = cnt & 0xffff, nvl = cnt >> 16;
    cexc[tid] = sWoff[wrp] + inc - cs;   // exclusive prefix of chunk sums

    bool valid = (npk >= 1) && (nvl >= 2);
    float PA = 0.f, A2 = 0.f, A1 = 0.f, PH = 0.f, PWHH = 0.f;

    if (valid) {
        float sp0 = smf[XIDX(p0)];
        float sv0 = smf[XIDX(v0)];
        PH = sp0 - sv0;
        float hh = (sp0 + sv0) * 0.5f;

        // half-height indices: only over [v0, p0]
        int li = N, ri = -1;
        for (int i = v0 + tid; i <= p0; i += NT) {
            float c = smf[XIDX(i)];
            if (c >= hh) {
                if (i < p0) li = min(li, i);
                if (i > v0) ri = max(ri, i);
            }
        }
        li = __reduce_min_sync(0xffffffffu, li);
        ri = __reduce_max_sync(0xffffffffu, ri);
        if (lane == 0) { sP0[wrp] = li; sVl[wrp] = ri; }
        __syncthreads();                                 // barrier 3
        if (wrp == 0) {
            int a = (lane < 8) ? sP0[lane] : N;
            int b = (lane < 8) ? sVl[lane] : -1;
            a = __reduce_min_sync(0xffffffffu, a);
            b = __reduce_max_sync(0xffffffffu, b);
            if (lane == 0) { finI[1] = a; finI[2] = b; }
        }
        __syncthreads();                                 // barrier 4
        li = finI[1]; ri = finI[2];
        if (li == N)  li = v0;
        if (ri == -1) ri = p0;
        PWHH = (float)(ri - li) / SRf;

        // trapezoids via prefix point queries (warp 0 only)
        if (wrp == 0) {
            auto Pq = [&](int idx) -> float {
                int c = idx >> 5;
                float v = (lane <= (idx & 31)) ? smf[XIDX((c << 5) + lane)] : 0.f;
                #pragma unroll
                for (int o = 16; o; o >>= 1) v += __shfl_down_sync(0xffffffffu, v, o);
                v = __shfl_sync(0xffffffffu, v, 0);
                return cexc[c] + v;
            };
            float Pv0 = Pq(v0);
            PA = (Pq(vlast - 2) - Pv0 + 0.5f * (sv0 + smf[XIDX(vlast - 1)])) * (1.0f / SRf);
            if (v1 - 2 >= p0)
                A2 = (Pq(v1 - 2) - Pq(p0) + 0.5f * (sp0 + smf[XIDX(v1 - 1)])) * (1.0f / SRf);
            if (p0 - 2 >= v0)
                A1 = (Pq(p0 - 2) - Pv0 + 0.5f * (sv0 + smf[XIDX(p0 - 1)])) * (1.0f / SRf);
        }
    }
    __syncthreads();   // barrier 5: all smem reads done before FFT overwrites

    // ---- FFT: 4096-pt, 4 radix-8 DIF passes --------------------------------
    {
        float sn, csn;
        __sincosf(-2.0f * PI_F * (float)tid / 4096.0f, &sn, &csn);
        float2 tw = make_float2(csn, sn);
        bfly8<512, true>(z, tid, tw);
        const float2 wstep = make_float2(0.92387953251128674f, -0.38268343236508978f);
        float2 twb = cmul(tw, wstep);
        bfly8<512, true>(z, tid + 256, twb);
    }
    __syncthreads();                                     // barrier 6
    {
        int t = tid & 63;
        float sn, csn;
        __sincosf(-2.0f * PI_F * (float)t / 512.0f, &sn, &csn);
        float2 tw = make_float2(csn, sn);
        bfly8<64, true>(z, (tid >> 6) * 512 + t, tw);
        bfly8<64, true>(z, ((tid + 256) >> 6) * 512 + t, tw);
    }
    __syncthreads();                                     // barrier 7
    {
        int t = (tid >> 2) & 7;
        float sn, csn;
        __sincosf(-2.0f * PI_F * (float)t / 64.0f, &sn, &csn);
        float2 tw = make_float2(csn, sn);
        int blk0 = (tid & 3) + 4 * (tid >> 5);
        bfly8<8, true>(z, blk0 * 64 + t, tw);
        int blk1 = (tid & 3) + 4 * ((tid + 256) >> 5);
        bfly8<8, true>(z, blk1 * 64 + t, tw);
    }
    __syncthreads();                                     // barrier 8
    {
        float2 dummy = make_float2(1.f, 0.f);
        bfly8<1, false>(z, tid * 8, dummy);
        bfly8<1, false>(z, (tid + 256) * 8, dummy);
    }
    __syncthreads();                                     // barrier 9

    // ---- unpack real FFT + magnitude sum (conjugate-symmetry halved) -------
    float fs = 0.f;
    {
        int k0 = lane * 64 + wrp;
        float2 Wk;
        {
            float sn, csn;
            __sincosf(-PI_F * (float)k0 / (float)M, &sn, &csn);
            Wk = make_float2(csn, sn);
        }
        const float2 Wstep = make_float2(0.99998117528260111f, -0.0061358846491544753f);
        #pragma unroll
        for (int rep = 0; rep < 8; rep++) {
            int k  = k0 + 8 * rep;
            int km = (M - k) & (M - 1);
            float2 Zk = z[POFF(drev(k))];
            float2 Zm = z[POFF(drev(km))];
            float2 Ze = make_float2(0.5f * (Zk.x + Zm.x), 0.5f * (Zk.y - Zm.y));
            float2 Bv = make_float2(0.5f * (Zk.x - Zm.x), 0.5f * (Zk.y + Zm.y));
            float2 Zo = make_float2(Bv.y, -Bv.x);
            float2 WZo = cmul(Wk, Zo);
            float ax = Ze.x + WZo.x, ay = Ze.y + WZo.y;
            float bx = Ze.x - WZo.x, by = Ze.y - WZo.y;
            float mag = fsqrt_ap(ax * ax + ay * ay) + fsqrt_ap(bx * bx + by * by);
            fs += (k == 0) ? mag : 2.0f * mag;
            Wk = cmul(Wk, Wstep);
        }
        if (tid == 0) {
            float2 Zk = z[POFF(4)];                      // drev(2048) = 4
            fs += 2.0f * fsqrt_ap(Zk.x * Zk.x + Zk.y * Zk.y);
        }
    }
    // slim 2-barrier block sum
    #pragma unroll
    for (int o = 16; o; o >>= 1) fs += __shfl_down_sync(0xffffffffu, fs, o);
    if (lane == 0) sS2[wrp] = fs;
    __syncthreads();                                     // barrier 10
    if (wrp == 0) {
        float v = (lane < 8) ? sS2[lane] : 0.f;
        #pragma unroll
        for (int o = 16; o; o >>= 1) v += __shfl_down_sync(0xffffffffu, v, o);
        if (lane == 0) finF[0] = v;
    }
    __syncthreads();                                     // barrier 11

    // ---- write output ------------------------------------------------------
    if (tid == 0) {
        float fftm = finF[0] * (1.0f / (float)N);
        float s    = stot;
        float mean = s * (1.0f / (float)N);
        float var  = (s2 - s * mean) * (1.0f / (float)(N - 1));
        float sd   = sqrtf(var);
        float* o = out + (size_t)row * 10;
        o[0] = mx;
        o[1] = mx - mn;
        o[2] = var;
        o[3] = sd;
        o[4] = fftm;
        o[5] = valid ? PA : 0.f;
        o[6] = valid ? A2 : 0.f;
        o[7] = valid ? PH : 0.f;
        o[8] = valid ? A1 : 0.f;
        o[9] = valid ? PWHH : 0.f;
    }
}

extern "C" void kernel_launch(void* const* d_in, const int* in_sizes, int n_in,
                              void* d_out, int out_size) {
    const float* x = (const float*)d_in[0];
    float* out = (float*)d_out;
    int nrows = in_sizes[0] / N;  // 2048
    size_t smem_bytes = (size_t)SMEM_F2 * sizeof(float2);  // 34816 B
    cudaFuncSetAttribute(feat_kernel, cudaFuncAttributeMaxDynamicSharedMemorySize,
                         (int)smem_bytes);
    feat_kernel<<<nrows, NT, smem_bytes>>>(x, out, nrows);
}

// round 15
// speedup vs baseline: 6.6549x; 1.0781x over previous
#include <cuda_runtime.h>
#include <math.h>

#define N     8192          // real signal length
#define M     4096          // packed complex length
#define NT    256
#define SRf   30.0f
#define PI_F  3.14159265358979f
#define C8    0.70710678118654752f   // sqrt(2)/2

// padded complex offset: one extra float2 per 16 -> conflict-free (see R13)
#define POFF(n)  ((n) + ((n) >> 4))

#define SMEM_F2  (M + M / 16)        // 4352 float2 = 34816 B

__device__ __forceinline__ float fsqrt_ap(float x) {
    float r; asm("sqrt.approx.f32 %0, %1;" : "=f"(r) : "f"(x)); return r;
}

// monotonic float<->uint key (total order for non-NaN floats)
__device__ __forceinline__ unsigned fkey(float f) {
    unsigned u = __float_as_uint(f);
    return (u >> 31) ? ~u : (u | 0x80000000u);
}
__device__ __forceinline__ float unkey(unsigned k) {
    unsigned u = (k >> 31) ? (k & 0x7fffffffu) : ~k;
    return __uint_as_float(u);
}

// ---------------- complex helpers -------------------------------------------
__device__ __forceinline__ float2 cadd(float2 a, float2 b) { return make_float2(a.x + b.x, a.y + b.y); }
__device__ __forceinline__ float2 csub(float2 a, float2 b) { return make_float2(a.x - b.x, a.y - b.y); }
__device__ __forceinline__ float2 cmul(float2 a, float2 b) {
    return make_float2(a.x * b.x - a.y * b.y, a.x * b.y + a.y * b.x);
}

// radix-8 DIF butterfly core: x0..x7 in regs -> y0..y7, twiddled if TW.
template<bool TW>
__device__ __forceinline__ void bfly8_core(
    float2 x0, float2 x1, float2 x2, float2 x3,
    float2 x4, float2 x5, float2 x6, float2 x7,
    float2 tw1, float2* y)
{
    float2 t0 = cadd(x0, x4), t4 = csub(x0, x4);
    float2 t1 = cadd(x1, x5), t5 = csub(x1, x5);
    float2 t2 = cadd(x2, x6), t6 = csub(x2, x6);
    float2 t3 = cadd(x3, x7), t7 = csub(x3, x7);

    float2 u0 = cadd(t0, t2), u2 = csub(t0, t2);
    float2 u1 = cadd(t1, t3), u3 = csub(t1, t3);
    float2 y0 = cadd(u0, u1);
    float2 y4 = csub(u0, u1);
    float2 y2 = make_float2(u2.x + u3.y, u2.y - u3.x);
    float2 y6 = make_float2(u2.x - u3.y, u2.y + u3.x);

    float2 w0 = t4;
    float2 w1 = make_float2(C8 * (t5.x + t5.y), C8 * (t5.y - t5.x));
    float2 w2 = make_float2(t6.y, -t6.x);
    float2 w3 = make_float2(C8 * (t7.y - t7.x), -C8 * (t7.x + t7.y));
    float2 p0 = cadd(w0, w2), p2 = csub(w0, w2);
    float2 p1 = cadd(w1, w3), p3 = csub(w1, w3);
    float2 y1 = cadd(p0, p1);
    float2 y5 = csub(p0, p1);
    float2 y3 = make_float2(p2.x + p3.y, p2.y - p3.x);
    float2 y7 = make_float2(p2.x - p3.y, p2.y + p3.x);

    if (TW) {
        float2 tw2 = cmul(tw1, tw1);
        float2 tw3 = cmul(tw2, tw1);
        float2 tw4 = cmul(tw2, tw2);
        float2 tw5 = cmul(tw3, tw2);
        float2 tw6 = cmul(tw3, tw3);
        float2 tw7 = cmul(tw4, tw3);
        y1 = cmul(y1, tw1);
        y2 = cmul(y2, tw2);
        y3 = cmul(y3, tw3);
        y4 = cmul(y4, tw4);
        y5 = cmul(y5, tw5);
        y6 = cmul(y6, tw6);
        y7 = cmul(y7, tw7);
    }
    y[0] = y0; y[1] = y1; y[2] = y2; y[3] = y3;
    y[4] = y4; y[5] = y5; y[6] = y6; y[7] = y7;
}

// smem->smem butterfly at 'base' with stride S
template<int S, bool TW>
__device__ __forceinline__ void bfly8(float2* __restrict__ z, int base, float2 tw1) {
    float2 y[8];
    bfly8_core<TW>(z[POFF(base + 0 * S)], z[POFF(base + 1 * S)],
                   z[POFF(base + 2 * S)], z[POFF(base + 3 * S)],
                   z[POFF(base + 4 * S)], z[POFF(base + 5 * S)],
                   z[POFF(base + 6 * S)], z[POFF(base + 7 * S)], tw1, y);
    #pragma unroll
    for (int j = 0; j < 8; j++) z[POFF(base + j * S)] = y[j];
}

// first pass: inputs straight from GMEM (coalesced, stride-512 complex), out to smem
__device__ __forceinline__ void bfly8_first(float2* __restrict__ z,
                                            const float2* __restrict__ xz,
                                            int base, float2 tw1) {
    float2 y[8];
    bfly8_core<true>(xz[base + 0 * 512], xz[base + 1 * 512],
                     xz[base + 2 * 512], xz[base + 3 * 512],
                     xz[base + 4 * 512], xz[base + 5 * 512],
                     xz[base + 6 * 512], xz[base + 7 * 512], tw1, y);
    #pragma unroll
    for (int j = 0; j < 8; j++) z[POFF(base + j * 512)] = y[j];
}

// octal digit reverse of 12-bit index
__device__ __forceinline__ int drev(int k) {
    return ((k & 7) << 9) | (((k >> 3) & 7) << 6) | (((k >> 6) & 7) << 3) | ((k >> 9) & 7);
}

// peak/valley classifier for element i with value Cv, neighbors Lv/Rv
#define CLASSIFY(Lv, Cv, Rv, i)                                        \
    do {                                                               \
        if ((Cv) > (Lv) && (Cv) > (Rv)) {                              \
            cnt += 1;                                                  \
            if (p0 == N) p0 = (i);                                     \
        } else if ((Cv) < (Lv) && (Cv) < (Rv)) {                       \
            cnt += (1 << 16);                                          \
            if (vs1 == N) vs1 = (i);                                   \
            else if (vs2 == N) vs2 = (i);                              \
            vlast = (i);                                               \
        }                                                              \
    } while (0)

// ---------------- main kernel: one CTA per row -------------------------------
__global__ __launch_bounds__(NT, 4)
void feat_kernel(const float* __restrict__ xin, float* __restrict__ out, int nrows) {
    extern __shared__ float smf[];           // SMEM_F2 float2 = 34816 B
    float2* z = (float2*)smf;
    // fused-reduction scratch
    __shared__ unsigned sKmx[8], sKmn[8];
    __shared__ float    sS2[8], sWt[8], sWoff[8];
    __shared__ int      sCnt[8], sP0[8], sVl[8], sV1[8], sV2[8];
    __shared__ float    finF[4];             // mx, mn, s2, stot
    __shared__ int      finI[5];             // cnt, p0, vlast, vs1, vs2
    __shared__ float    cexc[NT];            // exclusive prefix over chunks

    int row = blockIdx.x;
    if (row >= nrows) return;
    const float*  xr = xin + (size_t)row * N;
    const float4* x4 = (const float4*)xr;
    const float2* xz = (const float2*)xr;    // xz[n] = (x[2n], x[2n+1]) = z[n]
    int tid  = threadIdx.x;
    int lane = tid & 31;
    int wrp  = tid >> 5;

    // ---- pass 1 (registers only): stats + classify over chunk [32t,32t+31] --
    float mx = -3.4e38f, mn = 3.4e38f, s2 = 0.f, cs = 0.f;
    int cnt = 0;                 // npk + (nvl<<16)
    int p0 = N, vs1 = N, vs2 = N, vlast = -1;
    int base = 32 * tid;
    float xm1 = (tid > 0)      ? xr[base - 1]  : 0.f;
    float xp1 = (tid < NT - 1) ? xr[base + 32] : 0.f;
    float L = xm1, C = 0.f;
    #pragma unroll
    for (int rep = 0; rep < 8; rep++) {
        float4 f = x4[tid * 8 + rep];
        mx = fmaxf(fmaxf(mx, f.x), fmaxf(f.y, fmaxf(f.z, f.w)));
        mn = fminf(fminf(mn, f.x), fminf(f.y, fminf(f.z, f.w)));
        s2 += (f.x * f.x + f.y * f.y) + (f.z * f.z + f.w * f.w);
        cs += (f.x + f.y) + (f.z + f.w);
        if (rep == 0) {
            if (tid > 0) CLASSIFY(L, f.x, f.y, base);
            CLASSIFY(f.x, f.y, f.z, base + 1);
            CLASSIFY(f.y, f.z, f.w, base + 2);
        } else {
            CLASSIFY(L, C, f.x, base + 4 * rep - 1);
            CLASSIFY(C, f.x, f.y, base + 4 * rep);
            CLASSIFY(f.x, f.y, f.z, base + 4 * rep + 1);
            CLASSIFY(f.y, f.z, f.w, base + 4 * rep + 2);
        }
        L = f.z; C = f.w;
    }
    if (tid < NT - 1) CLASSIFY(L, C, xp1, base + 31);

    // ---- fused reduction, phase A: per-warp, zero barriers -----------------
    unsigned kmx = __reduce_max_sync(0xffffffffu, fkey(mx));
    unsigned kmn = __reduce_min_sync(0xffffffffu, fkey(mn));
    float s2w = s2;
    #pragma unroll
    for (int o = 16; o; o >>= 1) s2w += __shfl_down_sync(0xffffffffu, s2w, o);
    unsigned rcnt = __reduce_add_sync(0xffffffffu, (unsigned)cnt);
    int rp0 = __reduce_min_sync(0xffffffffu, p0);
    int rvl = __reduce_max_sync(0xffffffffu, vlast);
    int a1 = vs1, a2 = vs2;
    #pragma unroll
    for (int o = 16; o; o >>= 1) {
        int o1 = __shfl_down_sync(0xffffffffu, a1, o);
        int o2 = __shfl_down_sync(0xffffffffu, a2, o);
        int n1 = min(a1, o1);
        int n2 = min(max(a1, o1), min(a2, o2));
        a1 = n1; a2 = n2;
    }
    float inc = cs;
    #pragma unroll
    for (int o = 1; o < 32; o <<= 1) {
        float f = __shfl_up_sync(0xffffffffu, inc, o);
        if (lane >= o) inc += f;
    }
    if (lane == 0) {
        sKmx[wrp] = kmx; sKmn[wrp] = kmn; sS2[wrp] = s2w;
        sCnt[wrp] = (int)rcnt; sP0[wrp] = rp0; sVl[wrp] = rvl;
        sV1[wrp] = a1; sV2[wrp] = a2;
    }
    if (lane == 31) sWt[wrp] = inc;
    __syncthreads();                                     // barrier 1

    // ---- phase B: warp 0 combines across 8 warps ---------------------------
    if (wrp == 0) {
        unsigned bkmx = (lane < 8) ? sKmx[lane] : 0u;
        unsigned bkmn = (lane < 8) ? sKmn[lane] : 0xffffffffu;
        float    bs2  = (lane < 8) ? sS2[lane]  : 0.f;
        unsigned bcnt = (lane < 8) ? (unsigned)sCnt[lane] : 0u;
        int      bp0  = (lane < 8) ? sP0[lane]  : N;
        int      bvl  = (lane < 8) ? sVl[lane]  : -1;
        int      b1   = (lane < 8) ? sV1[lane]  : N;
        int      b2   = (lane < 8) ? sV2[lane]  : N;
        float    bwt  = (lane < 8) ? sWt[lane]  : 0.f;
        bkmx = __reduce_max_sync(0xffffffffu, bkmx);
        bkmn = __reduce_min_sync(0xffffffffu, bkmn);
        #pragma unroll
        for (int o = 16; o; o >>= 1) bs2 += __shfl_down_sync(0xffffffffu, bs2, o);
        bcnt = __reduce_add_sync(0xffffffffu, bcnt);
        bp0  = __reduce_min_sync(0xffffffffu, bp0);
        bvl  = __reduce_max_sync(0xffffffffu, bvl);
        #pragma unroll
        for (int o = 16; o; o >>= 1) {
            int o1 = __shfl_down_sync(0xffffffffu, b1, o);
            int o2 = __shfl_down_sync(0xffffffffu, b2, o);
            int n1 = min(b1, o1);
            int n2 = min(max(b1, o1), min(b2, o2));
            b1 = n1; b2 = n2;
        }
        float winc = bwt;
        #pragma unroll
        for (int o = 1; o < 32; o <<= 1) {
            float f = __shfl_up_sync(0xffffffffu, winc, o);
            if (lane >= o) winc += f;
        }
        if (lane < 8) sWoff[lane] = winc - bwt;
        if (lane == 7) finF[3] = winc;                   // stot
        if (lane == 0) {
            finF[0] = unkey(bkmx); finF[1] = unkey(bkmn); finF[2] = bs2;
            finI[0] = (int)bcnt; finI[1] = bp0; finI[2] = bvl;
            finI[3] = b1; finI[4] = b2;
        }
    }
    __syncthreads();                                     // barrier 2

    mx = finF[0]; mn = finF[1]; s2 = finF[2];
    float stot = finF[3];
    cnt   = finI[0];
    p0    = finI[1];
    vlast = finI[2];
    int v0 = finI[3], v1 = finI[4];
    int npk = cnt & 0xffff, nvl = cnt >> 16;
    cexc[tid] = sWoff[wrp] + inc - cs;   // exclusive prefix of chunk sums

    bool valid = (npk >= 1) && (nvl >= 2);
    float PA = 0.f, A2 = 0.f, A1 = 0.f, PH = 0.f, PWHH = 0.f;

    if (valid) {
        float sp0 = xr[p0];
        float sv0 = xr[v0];
        PH = sp0 - sv0;
        float hh = (sp0 + sv0) * 0.5f;

        // half-height indices: only over [v0, p0] (gmem, coalesced)
        int li = N, ri = -1;
        for (int i = v0 + tid; i <= p0; i += NT) {
            float c = xr[i];
            if (c >= hh) {
                if (i < p0) li = min(li, i);
                if (i > v0) ri = max(ri, i);
            }
        }
        li = __reduce_min_sync(0xffffffffu, li);
        ri = __reduce_max_sync(0xffffffffu, ri);
        if (lane == 0) { sP0[wrp] = li; sVl[wrp] = ri; }
        __syncthreads();                                 // barrier 3
        if (wrp == 0) {
            int a = (lane < 8) ? sP0[lane] : N;
            int b = (lane < 8) ? sVl[lane] : -1;
            a = __reduce_min_sync(0xffffffffu, a);
            b = __reduce_max_sync(0xffffffffu, b);
            if (lane == 0) { finI[1] = a; finI[2] = b; }
        }
        __syncthreads();                                 // barrier 4
        li = finI[1]; ri = finI[2];
        if (li == N)  li = v0;
        if (ri == -1) ri = p0;
        PWHH = (float)(ri - li) / SRf;

        // trapezoids via prefix point queries (warp 0 only; gmem reads)
        if (wrp == 0) {
            auto Pq = [&](int idx) -> float {
                int c = idx >> 5;
                float v = (lane <= (idx & 31)) ? xr[(c << 5) + lane] : 0.f;
                #pragma unroll
                for (int o = 16; o; o >>= 1) v += __shfl_down_sync(0xffffffffu, v, o);
                v = __shfl_sync(0xffffffffu, v, 0);
                return cexc[c] + v;
            };
            float Pv0 = Pq(v0);
            PA = (Pq(vlast - 2) - Pv0 + 0.5f * (sv0 + xr[vlast - 1])) * (1.0f / SRf);
            if (v1 - 2 >= p0)
                A2 = (Pq(v1 - 2) - Pq(p0) + 0.5f * (sp0 + xr[v1 - 1])) * (1.0f / SRf);
            if (p0 - 2 >= v0)
                A1 = (Pq(p0 - 2) - Pv0 + 0.5f * (sv0 + xr[p0 - 1])) * (1.0f / SRf);
        }
    }
    // NOTE: no barrier needed here — features touch only gmem + scratch, not z.

    // ---- FFT: 4096-pt, 4 radix-8 DIF passes; pass 1 reads GMEM directly ----
    {
        float sn, csn;
        __sincosf(-2.0f * PI_F * (float)tid / 4096.0f, &sn, &csn);
        float2 tw = make_float2(csn, sn);
        bfly8_first(z, xz, tid, tw);
        const float2 wstep = make_float2(0.92387953251128674f, -0.38268343236508978f);
        float2 twb = cmul(tw, wstep);
        bfly8_first(z, xz, tid + 256, twb);
    }
    __syncthreads();                                     // barrier 5
    {
        int t = tid & 63;
        float sn, csn;
        __sincosf(-2.0f * PI_F * (float)t / 512.0f, &sn, &csn);
        float2 tw = make_float2(csn, sn);
        bfly8<64, true>(z, (tid >> 6) * 512 + t, tw);
        bfly8<64, true>(z, ((tid + 256) >> 6) * 512 + t, tw);
    }
    __syncthreads();                                     // barrier 6
    {
        int t = (tid >> 2) & 7;
        float sn, csn;
        __sincosf(-2.0f * PI_F * (float)t / 64.0f, &sn, &csn);
        float2 tw = make_float2(csn, sn);
        int blk0 = (tid & 3) + 4 * (tid >> 5);
        bfly8<8, true>(z, blk0 * 64 + t, tw);
        int blk1 = (tid & 3) + 4 * ((tid + 256) >> 5);
        bfly8<8, true>(z, blk1 * 64 + t, tw);
    }
    __syncthreads();                                     // barrier 7
    {
        float2 dummy = make_float2(1.f, 0.f);
        bfly8<1, false>(z, tid * 8, dummy);
        bfly8<1, false>(z, (tid + 256) * 8, dummy);
    }
    __syncthreads();                                     // barrier 8

    // ---- unpack real FFT + magnitude sum (conjugate-symmetry halved) -------
    float fs = 0.f;
    {
        int k0 = lane * 64 + wrp;
        float2 Wk;
        {
            float sn, csn;
            __sincosf(-PI_F * (float)k0 / (float)M, &sn, &csn);
            Wk = make_float2(csn, sn);
        }
        const float2 Wstep = make_float2(0.99998117528260111f, -0.0061358846491544753f);
        #pragma unroll
        for (int rep = 0; rep < 8; rep++) {
            int k  = k0 + 8 * rep;
            int km = (M - k) & (M - 1);
            float2 Zk = z[POFF(drev(k))];
            float2 Zm = z[POFF(drev(km))];
            float2 Ze = make_float2(0.5f * (Zk.x + Zm.x), 0.5f * (Zk.y - Zm.y));
            float2 Bv = make_float2(0.5f * (Zk.x - Zm.x), 0.5f * (Zk.y + Zm.y));
            float2 Zo = make_float2(Bv.y, -Bv.x);
            float2 WZo = cmul(Wk, Zo);
            float ax = Ze.x + WZo.x, ay = Ze.y + WZo.y;
            float bx = Ze.x - WZo.x, by = Ze.y - WZo.y;
            float mag = fsqrt_ap(ax * ax + ay * ay) + fsqrt_ap(bx * bx + by * by);
            fs += (k == 0) ? mag : 2.0f * mag;
            Wk = cmul(Wk, Wstep);
        }
        if (tid == 0) {
            float2 Zk = z[POFF(4)];                      // drev(2048) = 4
            fs += 2.0f * fsqrt_ap(Zk.x * Zk.x + Zk.y * Zk.y);
        }
    }
    #pragma unroll
    for (int o = 16; o; o >>= 1) fs += __shfl_down_sync(0xffffffffu, fs, o);
    if (lane == 0) sS2[wrp] = fs;
    __syncthreads();                                     // barrier 9
    if (wrp == 0) {
        float v = (lane < 8) ? sS2[lane] : 0.f;
        #pragma unroll
        for (int o = 16; o; o >>= 1) v += __shfl_down_sync(0xffffffffu, v, o);
        if (lane == 0) finF[0] = v;
    }
    __syncthreads();                                     // barrier 10

    // ---- write output ------------------------------------------------------
    if (tid == 0) {
        float fftm = finF[0] * (1.0f / (float)N);
        float s    = stot;
        float mean = s * (1.0f / (float)N);
        float var  = (s2 - s * mean) * (1.0f / (float)(N - 1));
        float sd   = sqrtf(var);
        float* o = out + (size_t)row * 10;
        o[0] = mx;
        o[1] = mx - mn;
        o[2] = var;
        o[3] = sd;
        o[4] = fftm;
        o[5] = valid ? PA : 0.f;
        o[6] = valid ? A2 : 0.f;
        o[7] = valid ? PH : 0.f;
        o[8] = valid ? A1 : 0.f;
        o[9] = valid ? PWHH : 0.f;
    }
}

extern "C" void kernel_launch(void* const* d_in, const int* in_sizes, int n_in,
                              void* d_out, int out_size) {
    const float* x = (const float*)d_in[0];
    float* out = (float*)d_out;
    int nrows = in_sizes[0] / N;  // 2048
    size_t smem_bytes = (size_t)SMEM_F2 * sizeof(float2);  // 34816 B
    cudaFuncSetAttribute(feat_kernel, cudaFuncAttributeMaxDynamicSharedMemorySize,
                         (int)smem_bytes);
    feat_kernel<<<nrows, NT, smem_bytes>>>(x, out, nrows);
}

// round 16
// speedup vs baseline: 7.1260x; 1.0708x over previous
#include <cuda_runtime.h>
#include <math.h>

#define N     8192          // real signal length
#define M     4096          // packed complex length
#define NT    256
#define SRf   30.0f
#define PI_F  3.14159265358979f
#define C8    0.70710678118654752f   // sqrt(2)/2
#define W16C  0.92387953251128674f   // cos(2*pi/16)
#define W16S  0.38268343236508978f   // sin(2*pi/16)

// padded complex offset: one extra float2 per 16 -> conflict-free for all
// three radix-16 passes and the digit-reversed unpack (bank math in comments)
#define POFF(n)  ((n) + ((n) >> 4))

#define SMEM_F2  (M + M / 16)        // 4352 float2 = 34816 B

__device__ __forceinline__ float fsqrt_ap(float x) {
    float r; asm("sqrt.approx.f32 %0, %1;" : "=f"(r) : "f"(x)); return r;
}

// monotonic float<->uint key (total order for non-NaN floats)
__device__ __forceinline__ unsigned fkey(float f) {
    unsigned u = __float_as_uint(f);
    return (u >> 31) ? ~u : (u | 0x80000000u);
}
__device__ __forceinline__ float unkey(unsigned k) {
    unsigned u = (k >> 31) ? (k & 0x7fffffffu) : ~k;
    return __uint_as_float(u);
}

// ---------------- complex helpers -------------------------------------------
__device__ __forceinline__ float2 cadd(float2 a, float2 b) { return make_float2(a.x + b.x, a.y + b.y); }
__device__ __forceinline__ float2 csub(float2 a, float2 b) { return make_float2(a.x - b.x, a.y - b.y); }
__device__ __forceinline__ float2 cmul(float2 a, float2 b) {
    return make_float2(a.x * b.x - a.y * b.y, a.x * b.y + a.y * b.x);
}

// ---------------- 16-point DFT core (DIF, natural-order outputs) --------------
// stage 1: 4x DFT4 over strided sets {b, b+4, b+8, b+12} + internal twiddles
// w16^{b*q}; stage 2: 4x DFT4 over b. Output v[j] = X_j. If TW, v[j] *= tw1^j.
template<bool TW>
__device__ __forceinline__ void fft16_core(float2* v, float2 tw1) {
    float2 g[16];      // g[q*4 + b]
    #pragma unroll
    for (int b = 0; b < 4; b++) {
        float2 a0 = v[b], a1 = v[b + 4], a2 = v[b + 8], a3 = v[b + 12];
        float2 s0 = cadd(a0, a2), s1 = csub(a0, a2);
        float2 s2 = cadd(a1, a3), s3 = csub(a1, a3);
        float2 F0 = cadd(s0, s2);
        float2 F2 = csub(s0, s2);
        float2 F1 = make_float2(s1.x + s3.y, s1.y - s3.x);   // s1 - i*s3
        float2 F3 = make_float2(s1.x - s3.y, s1.y + s3.x);   // s1 + i*s3
        if (b == 0) {
            g[0] = F0; g[4] = F1; g[8] = F2; g[12] = F3;
        } else if (b == 1) {
            g[1]  = F0;
            g[5]  = cmul(F1, make_float2(W16C, -W16S));      // w^1
            g[9]  = cmul(F2, make_float2(C8,   -C8));        // w^2
            g[13] = cmul(F3, make_float2(W16S, -W16C));      // w^3
        } else if (b == 2) {
            g[2]  = F0;
            g[6]  = cmul(F1, make_float2(C8, -C8));          // w^2
            g[10] = make_float2(F2.y, -F2.x);                // w^4 = -i
            g[14] = cmul(F3, make_float2(-C8, -C8));         // w^6
        } else {
            g[3]  = F0;
            g[7]  = cmul(F1, make_float2(W16S, -W16C));      // w^3
            g[11] = cmul(F2, make_float2(-C8, -C8));         // w^6
            g[15] = cmul(F3, make_float2(-W16C, W16S));      // w^9 = -w
        }
    }
    #pragma unroll
    for (int q = 0; q < 4; q++) {
        float2 a0 = g[q * 4 + 0], a1 = g[q * 4 + 1];
        float2 a2 = g[q * 4 + 2], a3 = g[q * 4 + 3];
        float2 s0 = cadd(a0, a2), s1 = csub(a0, a2);
        float2 s2 = cadd(a1, a3), s3 = csub(a1, a3);
        v[q]      = cadd(s0, s2);                             // p=0
        v[4 + q]  = make_float2(s1.x + s3.y, s1.y - s3.x);    // p=1
        v[8 + q]  = csub(s0, s2);                             // p=2
        v[12 + q] = make_float2(s1.x - s3.y, s1.y + s3.x);    // p=3
    }
    if (TW) {
        float2 twr = tw1;
        v[1] = cmul(v[1], twr);
        #pragma unroll
        for (int j = 2; j < 16; j++) { twr = cmul(twr, tw1); v[j] = cmul(v[j], twr); }
    }
}

// smem->smem radix-16 butterfly at 'base' with stride S
template<int S, bool TW>
__device__ __forceinline__ void bfly16(float2* __restrict__ z, int base, float2 tw1) {
    float2 v[16];
    #pragma unroll
    for (int j = 0; j < 16; j++) v[j] = z[POFF(base + j * S)];
    fft16_core<TW>(v, tw1);
    #pragma unroll
    for (int j = 0; j < 16; j++) z[POFF(base + j * S)] = v[j];
}

// first pass: inputs straight from GMEM (coalesced, stride-256 complex)
__device__ __forceinline__ void bfly16_first(float2* __restrict__ z,
                                             const float2* __restrict__ xz,
                                             int t, float2 tw1) {
    float2 v[16];
    #pragma unroll
    for (int j = 0; j < 16; j++) v[j] = xz[t + j * 256];
    fft16_core<true>(v, tw1);
    #pragma unroll
    for (int j = 0; j < 16; j++) z[POFF(t + j * 256)] = v[j];
}

// hex digit reverse of 12-bit index (3 radix-16 passes -> digit-reversed)
__device__ __forceinline__ int drev16(int k) {
    return ((k & 15) << 8) | (k & 0x0F0) | ((k >> 8) & 15);
}

// peak/valley classifier for element i with value Cv, neighbors Lv/Rv
#define CLASSIFY(Lv, Cv, Rv, i)                                        \
    do {                                                               \
        if ((Cv) > (Lv) && (Cv) > (Rv)) {                              \
            cnt += 1;                                                  \
            if (p0 == N) p0 = (i);                                     \
        } else if ((Cv) < (Lv) && (Cv) < (Rv)) {                       \
            cnt += (1 << 16);                                          \
            if (vs1 == N) vs1 = (i);                                   \
            else if (vs2 == N) vs2 = (i);                              \
            vlast = (i);                                               \
        }                                                              \
    } while (0)

// ---------------- main kernel: one CTA per row -------------------------------
__global__ __launch_bounds__(NT, 4)
void feat_kernel(const float* __restrict__ xin, float* __restrict__ out, int nrows) {
    extern __shared__ float smf[];           // SMEM_F2 float2 = 34816 B
    float2* z = (float2*)smf;
    // fused-reduction scratch
    __shared__ unsigned sKmx[8], sKmn[8];
    __shared__ float    sS2[8], sWt[8], sWoff[8];
    __shared__ int      sCnt[8], sP0[8], sVl[8], sV1[8], sV2[8];
    __shared__ float    finF[4];             // mx, mn, s2, stot
    __shared__ int      finI[5];             // valid, p0, vlast, v0, v1
    __shared__ float    featF[6];            // PA, A2, A1, PH, PWHH, fsTot
    __shared__ float    cexc[NT];            // exclusive prefix over chunks

    int row = blockIdx.x;
    if (row >= nrows) return;
    const float*  xr = xin + (size_t)row * N;
    const float4* x4 = (const float4*)xr;
    const float2* xz = (const float2*)xr;    // xz[n] = (x[2n], x[2n+1]) = z[n]
    int tid  = threadIdx.x;
    int lane = tid & 31;
    int wrp  = tid >> 5;

    // ---- pass 1 (registers only): stats + classify over chunk [32t,32t+31] --
    float mx = -3.4e38f, mn = 3.4e38f, s2 = 0.f, cs = 0.f;
    int cnt = 0;                 // npk + (nvl<<16)
    int p0 = N, vs1 = N, vs2 = N, vlast = -1;
    int base = 32 * tid;
    float xm1 = (tid > 0)      ? xr[base - 1]  : 0.f;
    float xp1 = (tid < NT - 1) ? xr[base + 32] : 0.f;
    float L = xm1, C = 0.f;
    #pragma unroll
    for (int rep = 0; rep < 8; rep++) {
        float4 f = x4[tid * 8 + rep];
        mx = fmaxf(fmaxf(mx, f.x), fmaxf(f.y, fmaxf(f.z, f.w)));
        mn = fminf(fminf(mn, f.x), fminf(f.y, fminf(f.z, f.w)));
        s2 += (f.x * f.x + f.y * f.y) + (f.z * f.z + f.w * f.w);
        cs += (f.x + f.y) + (f.z + f.w);
        if (rep == 0) {
            if (tid > 0) CLASSIFY(L, f.x, f.y, base);
            CLASSIFY(f.x, f.y, f.z, base + 1);
            CLASSIFY(f.y, f.z, f.w, base + 2);
        } else {
            CLASSIFY(L, C, f.x, base + 4 * rep - 1);
            CLASSIFY(C, f.x, f.y, base + 4 * rep);
            CLASSIFY(f.x, f.y, f.z, base + 4 * rep + 1);
            CLASSIFY(f.y, f.z, f.w, base + 4 * rep + 2);
        }
        L = f.z; C = f.w;
    }
    if (tid < NT - 1) CLASSIFY(L, C, xp1, base + 31);

    // ---- fused reduction, phase A: per-warp, zero barriers -----------------
    unsigned kmx = __reduce_max_sync(0xffffffffu, fkey(mx));
    unsigned kmn = __reduce_min_sync(0xffffffffu, fkey(mn));
    float s2w = s2;
    #pragma unroll
    for (int o = 16; o; o >>= 1) s2w += __shfl_down_sync(0xffffffffu, s2w, o);
    unsigned rcnt = __reduce_add_sync(0xffffffffu, (unsigned)cnt);
    int rp0 = __reduce_min_sync(0xffffffffu, p0);
    int rvl = __reduce_max_sync(0xffffffffu, vlast);
    int a1 = vs1, a2 = vs2;
    #pragma unroll
    for (int o = 16; o; o >>= 1) {
        int o1 = __shfl_down_sync(0xffffffffu, a1, o);
        int o2 = __shfl_down_sync(0xffffffffu, a2, o);
        int n1 = min(a1, o1);
        int n2 = min(max(a1, o1), min(a2, o2));
        a1 = n1; a2 = n2;
    }
    float inc = cs;
    #pragma unroll
    for (int o = 1; o < 32; o <<= 1) {
        float f = __shfl_up_sync(0xffffffffu, inc, o);
        if (lane >= o) inc += f;
    }
    if (lane == 0) {
        sKmx[wrp] = kmx; sKmn[wrp] = kmn; sS2[wrp] = s2w;
        sCnt[wrp] = (int)rcnt; sP0[wrp] = rp0; sVl[wrp] = rvl;
        sV1[wrp] = a1; sV2[wrp] = a2;
    }
    if (lane == 31) sWt[wrp] = inc;
    __syncthreads();                                     // barrier 1

    // ---- phase B: warp 0 combines across 8 warps ---------------------------
    if (wrp == 0) {
        unsigned bkmx = (lane < 8) ? sKmx[lane] : 0u;
        unsigned bkmn = (lane < 8) ? sKmn[lane] : 0xffffffffu;
        float    bs2  = (lane < 8) ? sS2[lane]  : 0.f;
        unsigned bcnt = (lane < 8) ? (unsigned)sCnt[lane] : 0u;
        int      bp0  = (lane < 8) ? sP0[lane]  : N;
        int      bvl  = (lane < 8) ? sVl[lane]  : -1;
        int      b1   = (lane < 8) ? sV1[lane]  : N;
        int      b2   = (lane < 8) ? sV2[lane]  : N;
        float    bwt  = (lane < 8) ? sWt[lane]  : 0.f;
        bkmx = __reduce_max_sync(0xffffffffu, bkmx);
        bkmn = __reduce_min_sync(0xffffffffu, bkmn);
        #pragma unroll
        for (int o = 16; o; o >>= 1) bs2 += __shfl_down_sync(0xffffffffu, bs2, o);
        bcnt = __reduce_add_sync(0xffffffffu, bcnt);
        bp0  = __reduce_min_sync(0xffffffffu, bp0);
        bvl  = __reduce_max_sync(0xffffffffu, bvl);
        #pragma unroll
        for (int o = 16; o; o >>= 1) {
            int o1 = __shfl_down_sync(0xffffffffu, b1, o);
            int o2 = __shfl_down_sync(0xffffffffu, b2, o);
            int n1 = min(b1, o1);
            int n2 = min(max(b1, o1), min(b2, o2));
            b1 = n1; b2 = n2;
        }
        float winc = bwt;
        #pragma unroll
        for (int o = 1; o < 32; o <<= 1) {
            float f = __shfl_up_sync(0xffffffffu, winc, o);
            if (lane >= o) winc += f;
        }
        if (lane < 8) sWoff[lane] = winc - bwt;
        if (lane == 7) finF[3] = winc;                   // stot
        if (lane == 0) {
            finF[0] = unkey(bkmx); finF[1] = unkey(bkmn); finF[2] = bs2;
            int npk = (int)(bcnt & 0xffffu), nvl = (int)(bcnt >> 16);
            finI[0] = (npk >= 1 && nvl >= 2) ? 1 : 0;
            finI[1] = bp0; finI[2] = bvl;
            finI[3] = b1; finI[4] = b2;
        }
    }
    __syncthreads();                                     // barrier 2

    bool valid = finI[0] != 0;
    p0    = finI[1];
    vlast = finI[2];
    int v0 = finI[3], v1 = finI[4];
    cexc[tid] = sWoff[wrp] + inc - cs;   // exclusive prefix of chunk sums
    if (tid < 6) featF[tid] = 0.f;       // default feature outputs (invalid case)

    if (valid) {
        float sp0 = xr[p0];
        float sv0 = xr[v0];
        float hh = (sp0 + sv0) * 0.5f;

        // half-height indices: only over [v0, p0] (gmem, coalesced)
        int li = N, ri = -1;
        for (int i = v0 + tid; i <= p0; i += NT) {
            float c = xr[i];
            if (c >= hh) {
                if (i < p0) li = min(li, i);
                if (i > v0) ri = max(ri, i);
            }
        }
        li = __reduce_min_sync(0xffffffffu, li);
        ri = __reduce_max_sync(0xffffffffu, ri);
        if (lane == 0) { sP0[wrp] = li; sVl[wrp] = ri; }
        __syncthreads();                                 // barrier 3
        if (wrp == 0) {
            int a = (lane < 8) ? sP0[lane] : N;
            int b = (lane < 8) ? sVl[lane] : -1;
            a = __reduce_min_sync(0xffffffffu, a);
            b = __reduce_max_sync(0xffffffffu, b);
            if (lane == 0) { finI[1] = a; finI[2] = b; }
        }
        __syncthreads();                                 // barrier 4

        // trapezoids + scalar features (warp 0 only; gmem reads)
        if (wrp == 0) {
            int li2 = finI[1], ri2 = finI[2];
            if (li2 == N)  li2 = v0;
            if (ri2 == -1) ri2 = p0;
            auto Pq = [&](int idx) -> float {
                int c = idx >> 5;
                float v = (lane <= (idx & 31)) ? xr[(c << 5) + lane] : 0.f;
                #pragma unroll
                for (int o = 16; o; o >>= 1) v += __shfl_down_sync(0xffffffffu, v, o);
                v = __shfl_sync(0xffffffffu, v, 0);
                return cexc[c] + v;
            };
            float Pv0 = Pq(v0);
            float PA = (Pq(vlast - 2) - Pv0 + 0.5f * (sv0 + xr[vlast - 1])) * (1.0f / SRf);
            float A2 = 0.f, A1 = 0.f;
            if (v1 - 2 >= p0)
                A2 = (Pq(v1 - 2) - Pq(p0) + 0.5f * (sp0 + xr[v1 - 1])) * (1.0f / SRf);
            if (p0 - 2 >= v0)
                A1 = (Pq(p0 - 2) - Pv0 + 0.5f * (sv0 + xr[p0 - 1])) * (1.0f / SRf);
            if (lane == 0) {
                featF[0] = PA;
                featF[1] = A2;
                featF[2] = A1;
                featF[3] = sp0 - sv0;                        // PH
                featF[4] = (float)(ri2 - li2) / SRf;         // PWHH
            }
        }
    }
    // no barrier needed: features touch only gmem + scratch arrays, not z

    // ---- FFT: 4096-pt, 3 radix-16 DIF passes; pass 1 reads GMEM directly ---
    {   // pass 1: L=4096, S=256, t = tid
        float sn, csn;
        __sincosf(-2.0f * PI_F * (float)tid / 4096.0f, &sn, &csn);
        bfly16_first(z, xz, tid, make_float2(csn, sn));
    }
    __syncthreads();                                     // barrier 5
    {   // pass 2: L=256, S=16, t = tid&15, blk = tid>>4
        int t = tid & 15;
        float sn, csn;
        __sincosf(-2.0f * PI_F * (float)t / 256.0f, &sn, &csn);
        bfly16<16, true>(z, (tid >> 4) * 256 + t, make_float2(csn, sn));
    }
    __syncthreads();                                     // barrier 6
    {   // pass 3: L=16, S=1, twiddle-free
        bfly16<1, false>(z, tid * 16, make_float2(1.f, 0.f));
    }
    __syncthreads();                                     // barrier 7

    // ---- unpack real FFT + magnitude sum (conjugate-symmetry halved) -------
    // total = (a0+b0) + 2*sum_{k=1..2047}(a_k+b_k) + 2*|X[2048]|
    // lane->k map k = lane*64 + wrp*8 + rep: storage drev16(k) gives banks
    // 2*(lane[1:0]*4 + lane[4:2]) + C per phase -> fully conflict-free.
    float fs = 0.f;
    {
        int k0 = lane * 64 + wrp * 8;
        float2 Wk;
        {
            float sn, csn;
            __sincosf(-PI_F * (float)k0 / (float)M, &sn, &csn);
            Wk = make_float2(csn, sn);
        }
        // step = exp(-i*pi/4096)
        const float2 Wstep = make_float2(0.99999970586288222f, -0.00076699031874414f);
        #pragma unroll
        for (int rep = 0; rep < 8; rep++) {
            int k  = k0 + rep;
            int km = (M - k) & (M - 1);
            float2 Zk = z[POFF(drev16(k))];
            float2 Zm = z[POFF(drev16(km))];
            float2 Ze = make_float2(0.5f * (Zk.x + Zm.x), 0.5f * (Zk.y - Zm.y));
            float2 Bv = make_float2(0.5f * (Zk.x - Zm.x), 0.5f * (Zk.y + Zm.y));
            float2 Zo = make_float2(Bv.y, -Bv.x);
            float2 WZo = cmul(Wk, Zo);
            float ax = Ze.x + WZo.x, ay = Ze.y + WZo.y;
            float bx = Ze.x - WZo.x, by = Ze.y - WZo.y;
            float mag = fsqrt_ap(ax * ax + ay * ay) + fsqrt_ap(bx * bx + by * by);
            fs += (k == 0) ? mag : 2.0f * mag;
            Wk = cmul(Wk, Wstep);
        }
        if (tid == 0) {
            float2 Zk = z[POFF(8)];                      // drev16(2048) = 8
            fs += 2.0f * fsqrt_ap(Zk.x * Zk.x + Zk.y * Zk.y);
        }
    }
    #pragma unroll
    for (int o = 16; o; o >>= 1) fs += __shfl_down_sync(0xffffffffu, fs, o);
    if (lane == 0) sS2[wrp] = fs;
    __syncthreads();                                     // barrier 8
    if (wrp == 0) {
        float v = (lane < 8) ? sS2[lane] : 0.f;
        #pragma unroll
        for (int o = 16; o; o >>= 1) v += __shfl_down_sync(0xffffffffu, v, o);
        if (lane == 0) featF[5] = v;
    }
    __syncthreads();                                     // barrier 9

    // ---- write output ------------------------------------------------------
    if (tid == 0) {
        float s    = finF[3];
        float mean = s * (1.0f / (float)N);
        float var  = (finF[2] - s * mean) * (1.0f / (float)(N - 1));
        float sd   = sqrtf(var);
        float* o = out + (size_t)row * 10;
        o[0] = finF[0];
        o[1] = finF[0] - finF[1];
        o[2] = var;
        o[3] = sd;
        o[4] = featF[5] * (1.0f / (float)N);
        o[5] = featF[0];
        o[6] = featF[1];
        o[7] = featF[3];
        o[8] = featF[2];
        o[9] = featF[4];
    }
}

extern "C" void kernel_launch(void* const* d_in, const int* in_sizes, int n_in,
                              void* d_out, int out_size) {
    const float* x = (const float*)d_in[0];
    float* out = (float*)d_out;
    int nrows = in_sizes[0] / N;  // 2048
    size_t smem_bytes = (size_t)SMEM_F2 * sizeof(float2);  // 34816 B
    cudaFuncSetAttribute(feat_kernel, cudaFuncAttributeMaxDynamicSharedMemorySize,
                         (int)smem_bytes);
    feat_kernel<<<nrows, NT, smem_bytes>>>(x, out, nrows);
}